// round 14
// baseline (speedup 1.0000x reference)
#include <cuda_runtime.h>
#include <cuda_bf16.h>
#include <math.h>
#include <cstdint>

// ---------------- problem constants ----------------
#define BB   64
#define TT   512
#define DD   512
#define HH   256
#define MS   64
#define ML   8
#define NST  64
#define G4   1024
#define NCOL 2048
#define NSPAN (BB*MS)        // 4096
#define NPOS  (NSPAN*ML)     // 32768
#define NBLK 148             // persistent grid (<= SM count -> all resident)

// ---------------- device scratch ----------------
__device__ int   d_nvalid;
__device__ int   d_actcount[8];
__device__ int   g_arrive;
__device__ int   d_len_g[NSPAN];
__device__ int   d_srcidx_g[NPOS];
__device__ int   d_rowidx_g[NPOS];
__device__ int   d_actlist_g[8][NSPAN];
__device__ __nv_bfloat16 d_Wh[(size_t)NCOL*DD];     // W_ih hi split [n][k]
__device__ __nv_bfloat16 d_Wl[(size_t)NCOL*DD];     // lo
__device__ __nv_bfloat16 d_Whh_h[(size_t)NCOL*HH];  // W_hh hi split [n][k] gate-interleaved
__device__ __nv_bfloat16 d_Whh_l[(size_t)NCOL*HH];  // lo
__device__ float d_bcat[NCOL];
__device__ float d_sembT[DD*NST];
__device__ float d_XG[(size_t)NPOS*NCOL];    // gate-interleaved input gates
__device__ float d_hbuf[2][NSPAN*2*HH];      // ping-pong h
__device__ float d_c[NSPAN*2*HH];
__device__ float d_pooled[NSPAN*2*HH];

__device__ __forceinline__ float sigf(float x){ return 1.0f/(1.0f+__expf(-x)); }

__device__ __forceinline__ void cp16(void* dst, const void* src){
    unsigned int d = (unsigned int)__cvta_generic_to_shared(dst);
    asm volatile("cp.async.cg.shared.global [%0], [%1], 16;\n" :: "r"(d), "l"(src));
}
__device__ __forceinline__ void cp_commit(){ asm volatile("cp.async.commit_group;\n"); }
__device__ __forceinline__ void cp_wait0(){ asm volatile("cp.async.wait_group 0;\n"); }

__device__ __forceinline__ uint32_t smem_u32(const void* p){
    uint32_t a;
    asm("{ .reg .u64 t; cvta.to.shared.u64 t, %1; cvt.u32.u64 %0, t; }" : "=r"(a) : "l"(p));
    return a;
}
__device__ __forceinline__ void ldm4(uint32_t* r, uint32_t addr){
    asm volatile("ldmatrix.sync.aligned.m8n8.x4.shared.b16 {%0,%1,%2,%3}, [%4];"
        : "=r"(r[0]),"=r"(r[1]),"=r"(r[2]),"=r"(r[3]) : "r"(addr));
}
__device__ __forceinline__ void mma16816(float* c, const uint32_t* a, const uint32_t* b){
    asm volatile("mma.sync.aligned.m16n8k16.row.col.f32.bf16.bf16.f32 "
        "{%0,%1,%2,%3}, {%4,%5,%6,%7}, {%8,%9}, {%0,%1,%2,%3};"
        : "+f"(c[0]),"+f"(c[1]),"+f"(c[2]),"+f"(c[3])
        : "r"(a[0]),"r"(a[1]),"r"(a[2]),"r"(a[3]), "r"(b[0]),"r"(b[1]));
}

// ---------------- weight prep (includes init; launched FIRST) ----------------
// gate-interleaved col n: dir = n>>10, r = n&1023 -> original row (r&3)*HH + (r>>2)
__global__ void k_prep(const float* __restrict__ Wih_f, const float* __restrict__ Wih_b,
                       const float* __restrict__ bf,    const float* __restrict__ bbias,
                       const float* __restrict__ Whh_f, const float* __restrict__ Whh_b,
                       const float* __restrict__ semb){
    if (blockIdx.x == 0){
        if (threadIdx.x == 0){ d_nvalid = 0; g_arrive = 0; }
        if (threadIdx.x < 8)  d_actcount[threadIdx.x] = 0;
    }
    int i = blockIdx.x*blockDim.x + threadIdx.x;
    int stride = gridDim.x*blockDim.x;
    for (int idx = i; idx < NCOL*DD; idx += stride){
        int n = idx / DD, k = idx % DD;
        int dir = n >> 10, r = n & (G4-1);
        int row = (r & 3)*HH + (r >> 2);
        float w = dir ? Wih_b[row*DD + k] : Wih_f[row*DD + k];
        __nv_bfloat16 h = __float2bfloat16(w);
        d_Wh[idx] = h;
        d_Wl[idx] = __float2bfloat16(w - __bfloat162float(h));
    }
    for (int idx = i; idx < NCOL*HH; idx += stride){
        int n = idx >> 8, k = idx & (HH-1);
        int dir = n >> 10, r = n & (G4-1);
        int row = (r & 3)*HH + (r >> 2);
        float w = dir ? Whh_b[row*HH + k] : Whh_f[row*HH + k];
        __nv_bfloat16 h = __float2bfloat16(w);
        d_Whh_h[idx] = h;
        d_Whh_l[idx] = __float2bfloat16(w - __bfloat162float(h));
    }
    for (int idx = i; idx < NCOL; idx += stride){
        int dir = idx >> 10, r = idx & (G4-1);
        int row = (r & 3)*HH + (r >> 2);
        d_bcat[idx] = dir ? bbias[row] : bf[row];
    }
    for (int idx = i; idx < DD*NST; idx += stride){
        int k = idx / NST, n = idx % NST;
        d_sembT[idx] = semb[n*DD + k];
    }
}

// ---------------- span packing (smem-staged scan) ----------------
__global__ void k_pack(const int* __restrict__ bio){
    int b = blockIdx.x;
    __shared__ int s_bio[TT];
    __shared__ int s_tok[MS][ML];
    __shared__ int s_cnt[MS];
    int tid = threadIdx.x;          // 64
    s_cnt[tid] = 0;
    for (int i = tid; i < TT; i += 64) s_bio[i] = bio[b*TT + i];
    __syncthreads();
    if (tid == 0){
        int sid = -1;
        for (int t = 0; t < TT; t++){
            int tag = s_bio[t];
            if (tag == 1) sid++;
            if ((tag == 1 || tag == 2) && sid >= 0 && sid < MS){
                int r = s_cnt[sid];
                if (r < ML) s_tok[sid][r] = t;
                s_cnt[sid] = r + 1;
            }
        }
    }
    __syncthreads();
    int s = tid;
    int len = min(s_cnt[s], ML);
    int span = b*MS + s;
    d_len_g[span] = len;
    if (len > 0){
        int base = atomicAdd(&d_nvalid, len);
        for (int r = 0; r < len; r++){
            d_srcidx_g[base+r] = b*TT + s_tok[s][r];
            d_rowidx_g[base+r] = span*ML + r;
        }
        for (int t = 1; t < ML; t++){
            if (len > t){
                int k = atomicAdd(&d_actcount[t], 1);
                d_actlist_g[t][k] = span;
            }
        }
    }
}

// ---------------- xg GEMM via mma.sync bf16 3-pass split (exact R6 kernel) ----------------
#define XPAD 40
#define ABUF (128*XPAD)      // elements per buffer

__global__ void __launch_bounds__(256) k_xg_mma(const float* __restrict__ X){
    int M = d_nvalid;
    int mBase = blockIdx.y * 128;
    if (mBase >= M) return;
    int nBase = blockIdx.x * 128;

    extern __shared__ __nv_bfloat16 sm[];
    __nv_bfloat16* Ah = sm;                  // [2][128][XPAD]
    __nv_bfloat16* Al = Ah + 2*ABUF;
    __nv_bfloat16* Bh = Al + 2*ABUF;
    __nv_bfloat16* Bl = Bh + 2*ABUF;
    int* s_sidx = (int*)(Bl + 2*ABUF);
    int* s_ridx = s_sidx + 128;

    int tid = threadIdx.x;
    if (tid < 128){
        int m = mBase + tid;
        bool v = (m < M);
        s_sidx[tid] = v ? d_srcidx_g[m]*DD : 0;
        s_ridx[tid] = v ? d_rowidx_g[m] : -1;
    }
    __syncthreads();

    int lane = tid & 31, w = tid >> 5;
    int wm = w & 3, wn = w >> 2;

    int lrow = tid >> 1, lhalf = tid & 1;
    int aoffs = lrow*XPAD + lhalf*16;
    const __nv_bfloat16* BhSrc = d_Wh + (size_t)(nBase + lrow)*DD + lhalf*16;
    const __nv_bfloat16* BlSrc = d_Wl + (size_t)(nBase + lrow)*DD + lhalf*16;
    const float* ASrc = X + s_sidx[lrow] + lhalf*16;

    int aRowOff = lane & 15;
    int aKOff   = (lane >> 4) * 8;
    int bNOff   = (lane & 7) + ((lane >> 4) << 3);
    int bKOff   = ((lane >> 3) & 1) * 8;

    uint32_t smbA_h = smem_u32(Ah), smbA_l = smem_u32(Al);
    uint32_t smbB_h = smem_u32(Bh), smbB_l = smem_u32(Bl);

    float acc[2][8][4];
    #pragma unroll
    for (int i=0;i<2;i++)
        #pragma unroll
        for (int j=0;j<8;j++)
            #pragma unroll
            for (int q=0;q<4;q++) acc[i][j][q]=0.f;

    {
        cp16(Bh + aoffs, BhSrc);       cp16(Bh + aoffs + 8, BhSrc + 8);
        cp16(Bl + aoffs, BlSrc);       cp16(Bl + aoffs + 8, BlSrc + 8);
        cp_commit();
        float4 v0 = *(const float4*)(ASrc + 0);
        float4 v1 = *(const float4*)(ASrc + 4);
        float4 v2 = *(const float4*)(ASrc + 8);
        float4 v3 = *(const float4*)(ASrc + 12);
        float fv[16] = {v0.x,v0.y,v0.z,v0.w, v1.x,v1.y,v1.z,v1.w,
                        v2.x,v2.y,v2.z,v2.w, v3.x,v3.y,v3.z,v3.w};
        __nv_bfloat16 hh[16], ll[16];
        #pragma unroll
        for (int q=0;q<16;q++){
            hh[q] = __float2bfloat16(fv[q]);
            ll[q] = __float2bfloat16(fv[q] - __bfloat162float(hh[q]));
        }
        *(uint4*)(Ah + aoffs)     = *(uint4*)(hh);
        *(uint4*)(Ah + aoffs + 8) = *(uint4*)(hh+8);
        *(uint4*)(Al + aoffs)     = *(uint4*)(ll);
        *(uint4*)(Al + aoffs + 8) = *(uint4*)(ll+8);
        cp_wait0();
        __syncthreads();
    }

    int p = 0;
    for (int kc = 0; kc < 16; kc++){
        float fv[16];
        bool more = (kc < 15);
        if (more){
            int nb = p ^ 1;
            int k0 = (kc+1)*32;
            int doffs = nb*ABUF + aoffs;
            cp16(Bh + doffs, BhSrc + k0);       cp16(Bh + doffs + 8, BhSrc + k0 + 8);
            cp16(Bl + doffs, BlSrc + k0);       cp16(Bl + doffs + 8, BlSrc + k0 + 8);
            cp_commit();
            float4 v0 = *(const float4*)(ASrc + k0 + 0);
            float4 v1 = *(const float4*)(ASrc + k0 + 4);
            float4 v2 = *(const float4*)(ASrc + k0 + 8);
            float4 v3 = *(const float4*)(ASrc + k0 + 12);
            fv[0]=v0.x; fv[1]=v0.y; fv[2]=v0.z; fv[3]=v0.w;
            fv[4]=v1.x; fv[5]=v1.y; fv[6]=v1.z; fv[7]=v1.w;
            fv[8]=v2.x; fv[9]=v2.y; fv[10]=v2.z; fv[11]=v2.w;
            fv[12]=v3.x; fv[13]=v3.y; fv[14]=v3.z; fv[15]=v3.w;
        }

        uint32_t baseAh = smbA_h + p*ABUF*2;
        uint32_t baseAl = smbA_l + p*ABUF*2;
        uint32_t baseBh = smbB_h + p*ABUF*2;
        uint32_t baseBl = smbB_l + p*ABUF*2;
        #pragma unroll
        for (int ks = 0; ks < 2; ks++){
            uint32_t ah[2][4], al[2][4];
            #pragma unroll
            for (int mt = 0; mt < 2; mt++){
                uint32_t eo = ((wm*32 + mt*16 + aRowOff)*XPAD + ks*16 + aKOff)*2;
                ldm4(ah[mt], baseAh + eo);
                ldm4(al[mt], baseAl + eo);
            }
            uint32_t bh[8][2], bl[8][2];
            #pragma unroll
            for (int g = 0; g < 4; g++){
                uint32_t eo = ((wn*64 + g*16 + bNOff)*XPAD + ks*16 + bKOff)*2;
                uint32_t r[4];
                ldm4(r, baseBh + eo);
                bh[2*g][0]=r[0]; bh[2*g][1]=r[1]; bh[2*g+1][0]=r[2]; bh[2*g+1][1]=r[3];
                ldm4(r, baseBl + eo);
                bl[2*g][0]=r[0]; bl[2*g][1]=r[1]; bl[2*g+1][0]=r[2]; bl[2*g+1][1]=r[3];
            }
            #pragma unroll
            for (int mt = 0; mt < 2; mt++)
                #pragma unroll
                for (int nt = 0; nt < 8; nt++){
                    mma16816(acc[mt][nt], ah[mt], bh[nt]);
                    mma16816(acc[mt][nt], ah[mt], bl[nt]);
                    mma16816(acc[mt][nt], al[mt], bh[nt]);
                }
        }

        if (more){
            int nb = p ^ 1;
            int doffs = nb*ABUF + aoffs;
            __nv_bfloat16 hh[16], ll[16];
            #pragma unroll
            for (int q=0;q<16;q++){
                hh[q] = __float2bfloat16(fv[q]);
                ll[q] = __float2bfloat16(fv[q] - __bfloat162float(hh[q]));
            }
            *(uint4*)(Ah + doffs)     = *(uint4*)(hh);
            *(uint4*)(Ah + doffs + 8) = *(uint4*)(hh+8);
            *(uint4*)(Al + doffs)     = *(uint4*)(ll);
            *(uint4*)(Al + doffs + 8) = *(uint4*)(ll+8);
            cp_wait0();
        }
        __syncthreads();
        p ^= 1;
    }

    #pragma unroll
    for (int mt = 0; mt < 2; mt++){
        int rl0 = wm*32 + mt*16 + (lane >> 2);
        #pragma unroll
        for (int half = 0; half < 2; half++){
            int rl = rl0 + half*8;
            int grow = s_ridx[rl];
            if (grow < 0) continue;
            float* dst = d_XG + (size_t)grow*NCOL + nBase;
            #pragma unroll
            for (int nt = 0; nt < 8; nt++){
                int col = wn*64 + nt*8 + (lane & 3)*2;
                float2 b2 = *(const float2*)(d_bcat + nBase + col);
                float2 o;
                o.x = acc[mt][nt][half*2+0] + b2.x;
                o.y = acc[mt][nt][half*2+1] + b2.y;
                *(float2*)(dst + col) = o;
            }
        }
    }
}
#define XSM_BYTES (8*ABUF*2 + 256*4)

// ---------------- persistent recurrence with tensor-core step GEMMs, K-chunk 64 ----------------
// tile: BM=32 spans x BN=128 gate-cols x K=256, bf16 hi/lo 3-pass mma.
// row byte stride 144 (72 bf16): ldmatrix bank starts 4r mod 32 -> conflict-free.
#define P_ABUFB 4608                 // 32*144
#define P_BBUFB 18432                // 128*144
#define P_AH 0                       // 2 buffers: 9216
#define P_AL 9216
#define P_BH 18432                   // 2 buffers: 36864
#define P_BL 55296
#define P_CS 92160                   // [32][132] float = 16896
#define P_SPN 109056
#define P_AOFF 109184
#define P_SLEN 109312
#define P_BYTES 109440

__global__ void __launch_bounds__(256) k_persist(){
    extern __shared__ char psm[];
    float* Cs = (float*)(psm + P_CS);            // [32][132]
    int* spn  = (int*)(psm + P_SPN);
    int* aoff = (int*)(psm + P_AOFF);
    int* slen = (int*)(psm + P_SLEN);
    uint32_t smb = smem_u32(psm);
    int tid = threadIdx.x, bid = blockIdx.x;
    int lane = tid & 31, w = tid >> 5;
    int wm = w & 1, wn = w >> 1;                 // 2 m-groups x 4 n-groups

    // ---- phase 0: step 0 pointwise ----
    for (int idx = bid*256 + tid; idx < NSPAN*2*HH; idx += NBLK*256){
        int span = idx >> 9;
        int rem  = idx & 511;
        int dir  = rem >> 8;
        int j    = rem & 255;
        int len  = d_len_g[span];
        if (len == 0){
            d_hbuf[0][idx] = 0.f; d_c[idx] = 0.f; d_pooled[idx] = 0.f;
        } else {
            int rank = dir ? (len-1) : 0;
            float4 g = *(const float4*)(d_XG + (size_t)(span*ML + rank)*NCOL + dir*G4 + j*4);
            float c = sigf(g.x) * tanhf(g.z);
            float h = sigf(g.w) * tanhf(c);
            d_c[idx] = c; d_hbuf[0][idx] = h; d_pooled[idx] = h;
        }
    }

    int aRowOff = lane & 15;
    int aKOff   = (lane >> 4) * 8;
    int bNOff   = (lane & 7) + ((lane >> 4) << 3);
    int bKOff   = ((lane >> 3) & 1) * 8;
    int arow = tid >> 3, ak = (tid & 7) * 8;     // A loader: row 0..31, 8 floats each

    for (int t = 1; t < ML; t++){
        // ---- global epoch barrier #t ----
        __syncthreads();
        if (tid == 0){
            __threadfence();
            atomicAdd(&g_arrive, 1);
            while (atomicAdd(&g_arrive, 0) < t*NBLK) { }
        }
        __syncthreads();

        int cnt = d_actcount[t];
        if (cnt <= 0) continue;
        const float* __restrict__ h_r = d_hbuf[(t-1)&1];
        float* __restrict__ h_w = d_hbuf[t&1];
        int nmt  = (cnt + 31) >> 5;
        int ntot = nmt * 16;

        for (int tile = bid; tile < ntot; tile += NBLK){
            int mt  = tile >> 4;
            int ct  = tile & 15;
            int dir = ct >> 3;
            int nb  = (ct & 7) * 128;

            __syncthreads();
            if (tid < 32){
                int m = mt*32 + tid;
                int span = (m < cnt) ? d_actlist_g[t][m] : -1;
                spn[tid] = span;
                int s0 = (span >= 0) ? span : 0;
                aoff[tid] = (s0*2 + dir)*HH;
                slen[tid] = d_len_g[s0];
            }
            __syncthreads();

            const __nv_bfloat16* WhhH = d_Whh_h + (size_t)(dir*G4 + nb)*HH;
            const __nv_bfloat16* WhhL = d_Whh_l + (size_t)(dir*G4 + nb)*HH;

            // ---- prologue: chunk 0 (K=64) into buffer 0 ----
            {
                #pragma unroll
                for (int li = 0; li < 4; li++){
                    int lin = tid + li*256;
                    int row = lin >> 3, seg = lin & 7;
                    cp16(psm + P_BH + row*144 + seg*16, WhhH + (size_t)row*HH + seg*8);
                    cp16(psm + P_BL + row*144 + seg*16, WhhL + (size_t)row*HH + seg*8);
                }
                cp_commit();
                float4 a0 = *(const float4*)(h_r + aoff[arow] + ak);
                float4 a1 = *(const float4*)(h_r + aoff[arow] + ak + 4);
                __nv_bfloat162 h0 = __floats2bfloat162_rn(a0.x, a0.y);
                __nv_bfloat162 h1 = __floats2bfloat162_rn(a0.z, a0.w);
                __nv_bfloat162 h2 = __floats2bfloat162_rn(a1.x, a1.y);
                __nv_bfloat162 h3 = __floats2bfloat162_rn(a1.z, a1.w);
                __nv_bfloat162 l0 = __floats2bfloat162_rn(a0.x - __bfloat162float(h0.x), a0.y - __bfloat162float(h0.y));
                __nv_bfloat162 l1 = __floats2bfloat162_rn(a0.z - __bfloat162float(h1.x), a0.w - __bfloat162float(h1.y));
                __nv_bfloat162 l2 = __floats2bfloat162_rn(a1.x - __bfloat162float(h2.x), a1.y - __bfloat162float(h2.y));
                __nv_bfloat162 l3 = __floats2bfloat162_rn(a1.z - __bfloat162float(h3.x), a1.w - __bfloat162float(h3.y));
                uint4 uh, ul;
                uh.x = *(uint32_t*)&h0; uh.y = *(uint32_t*)&h1; uh.z = *(uint32_t*)&h2; uh.w = *(uint32_t*)&h3;
                ul.x = *(uint32_t*)&l0; ul.y = *(uint32_t*)&l1; ul.z = *(uint32_t*)&l2; ul.w = *(uint32_t*)&l3;
                *(uint4*)(psm + P_AH + arow*144 + ak*2) = uh;
                *(uint4*)(psm + P_AL + arow*144 + ak*2) = ul;
                cp_wait0();
                __syncthreads();
            }

            float acc[4][4];
            #pragma unroll
            for (int i=0;i<4;i++)
                #pragma unroll
                for (int q=0;q<4;q++) acc[i][q]=0.f;

            int p = 0;
            for (int kc = 0; kc < 4; kc++){
                bool more = (kc < 3);
                if (more){
                    int nbuf = p ^ 1;
                    int k0 = (kc+1)*64;
                    #pragma unroll
                    for (int li = 0; li < 4; li++){
                        int lin = tid + li*256;
                        int row = lin >> 3, seg = lin & 7;
                        cp16(psm + P_BH + nbuf*P_BBUFB + row*144 + seg*16, WhhH + (size_t)row*HH + k0 + seg*8);
                        cp16(psm + P_BL + nbuf*P_BBUFB + row*144 + seg*16, WhhL + (size_t)row*HH + k0 + seg*8);
                    }
                    cp_commit();
                    float4 a0 = *(const float4*)(h_r + aoff[arow] + k0 + ak);
                    float4 a1 = *(const float4*)(h_r + aoff[arow] + k0 + ak + 4);
                    __nv_bfloat162 h0 = __floats2bfloat162_rn(a0.x, a0.y);
                    __nv_bfloat162 h1 = __floats2bfloat162_rn(a0.z, a0.w);
                    __nv_bfloat162 h2 = __floats2bfloat162_rn(a1.x, a1.y);
                    __nv_bfloat162 h3 = __floats2bfloat162_rn(a1.z, a1.w);
                    __nv_bfloat162 l0 = __floats2bfloat162_rn(a0.x - __bfloat162float(h0.x), a0.y - __bfloat162float(h0.y));
                    __nv_bfloat162 l1 = __floats2bfloat162_rn(a0.z - __bfloat162float(h1.x), a0.w - __bfloat162float(h1.y));
                    __nv_bfloat162 l2 = __floats2bfloat162_rn(a1.x - __bfloat162float(h2.x), a1.y - __bfloat162float(h2.y));
                    __nv_bfloat162 l3 = __floats2bfloat162_rn(a1.z - __bfloat162float(h3.x), a1.w - __bfloat162float(h3.y));
                    uint4 uh, ul;
                    uh.x = *(uint32_t*)&h0; uh.y = *(uint32_t*)&h1; uh.z = *(uint32_t*)&h2; uh.w = *(uint32_t*)&h3;
                    ul.x = *(uint32_t*)&l0; ul.y = *(uint32_t*)&l1; ul.z = *(uint32_t*)&l2; ul.w = *(uint32_t*)&l3;
                    *(uint4*)(psm + P_AH + nbuf*P_ABUFB + arow*144 + ak*2) = uh;
                    *(uint4*)(psm + P_AL + nbuf*P_ABUFB + arow*144 + ak*2) = ul;
                }

                uint32_t baseAh = smb + P_AH + p*P_ABUFB;
                uint32_t baseAl = smb + P_AL + p*P_ABUFB;
                uint32_t baseBh = smb + P_BH + p*P_BBUFB;
                uint32_t baseBl = smb + P_BL + p*P_BBUFB;
                #pragma unroll
                for (int ks = 0; ks < 4; ks++){
                    uint32_t ah[4], al[4];
                    uint32_t eoA = (wm*16 + aRowOff)*144 + (ks*16 + aKOff)*2;
                    ldm4(ah, baseAh + eoA);
                    ldm4(al, baseAl + eoA);
                    uint32_t bh[4][2], bl[4][2];
                    #pragma unroll
                    for (int g = 0; g < 2; g++){
                        uint32_t eo = (wn*32 + g*16 + bNOff)*144 + (ks*16 + bKOff)*2;
                        uint32_t r[4];
                        ldm4(r, baseBh + eo);
                        bh[2*g][0]=r[0]; bh[2*g][1]=r[1]; bh[2*g+1][0]=r[2]; bh[2*g+1][1]=r[3];
                        ldm4(r, baseBl + eo);
                        bl[2*g][0]=r[0]; bl[2*g][1]=r[1]; bl[2*g+1][0]=r[2]; bl[2*g+1][1]=r[3];
                    }
                    #pragma unroll
                    for (int nt = 0; nt < 4; nt++){
                        mma16816(acc[nt], ah, bh[nt]);
                        mma16816(acc[nt], ah, bl[nt]);
                        mma16816(acc[nt], al, bh[nt]);
                    }
                }

                if (more) cp_wait0();
                __syncthreads();
                p ^= 1;
            }

            // ---- stage accs to Cs [32][132] ----
            #pragma unroll
            for (int nt = 0; nt < 4; nt++){
                int col = wn*32 + nt*8 + (lane & 3)*2;
                int r0  = wm*16 + (lane >> 2);
                Cs[r0*132 + col]     = acc[nt][0];
                Cs[r0*132 + col + 1] = acc[nt][1];
                Cs[(r0+8)*132 + col]     = acc[nt][2];
                Cs[(r0+8)*132 + col + 1] = acc[nt][3];
            }
            __syncthreads();

            // ---- LSTM epilogue: each thread 4 (row,j) cells ----
            #pragma unroll
            for (int e = 0; e < 4; e++){
                int idx = tid + e*256;
                int row = idx >> 5, jj = idx & 31;
                int span = spn[row];
                if (span < 0) continue;
                float4 g4 = *(const float4*)&Cs[row*132 + jj*4];
                int rank = dir ? (slen[row]-1-t) : t;
                int j0 = (nb >> 2) + jj;
                float4 xg = *(const float4*)(d_XG + (size_t)(span*ML + rank)*NCOL + dir*G4 + j0*4);
                int he = (span*2 + dir)*HH + j0;
                float c = d_c[he];
                float gi = g4.x+xg.x, gf = g4.y+xg.y, gg = g4.z+xg.z, go = g4.w+xg.w;
                c = sigf(gf)*c + sigf(gi)*tanhf(gg);
                float h = sigf(go)*tanhf(c);
                d_c[he] = c;
                h_w[he] = h;
                d_pooled[he] += h;
            }
        }
    }
}

// ---------------- scoring GEMM: pooled [4096,512] x sembT [512,64] ----------------
__global__ void k_score(float* __restrict__ out){
    const int BM=64, BN=64, BK=16;
    int mBase = blockIdx.x * BM;
    __shared__ float As[BK][BM];
    __shared__ float Bs[BK][BN];
    int tid = threadIdx.x;
    float acc[4][4];
    #pragma unroll
    for (int i=0;i<4;i++)
        #pragma unroll
        for (int j=0;j<4;j++) acc[i][j]=0.f;
    int ty = tid >> 4, tx = tid & 15;
    for (int k0 = 0; k0 < DD; k0 += BK){
        {
            int row = tid >> 2;
            int kq  = (tid & 3) * 4;
            float4 v = *reinterpret_cast<const float4*>(d_pooled + (size_t)(mBase+row)*DD + k0 + kq);
            As[kq+0][row]=v.x; As[kq+1][row]=v.y; As[kq+2][row]=v.z; As[kq+3][row]=v.w;
        }
        {
            int kb = tid >> 4;
            int nq = (tid & 15) * 4;
            *reinterpret_cast<float4*>(&Bs[kb][nq]) =
                *reinterpret_cast<const float4*>(d_sembT + (size_t)(k0+kb)*NST + nq);
        }
        __syncthreads();
        #pragma unroll
        for (int kk=0; kk<BK; kk++){
            float a[4], b[4];
            *reinterpret_cast<float4*>(a) = *reinterpret_cast<float4*>(&As[kk][ty*4]);
            *reinterpret_cast<float4*>(b) = *reinterpret_cast<float4*>(&Bs[kk][tx*4]);
            #pragma unroll
            for (int i=0;i<4;i++)
                #pragma unroll
                for (int j=0;j<4;j++) acc[i][j] += a[i]*b[j];
        }
        __syncthreads();
    }
    #pragma unroll
    for (int i=0;i<4;i++){
        int r = mBase + ty*4 + i;
        #pragma unroll
        for (int j=0;j<4;j++)
            out[(size_t)r*NST + tx*4 + j] = acc[i][j];
    }
}

// ---------------- launch ----------------
extern "C" void kernel_launch(void* const* d_in, const int* in_sizes, int n_in,
                              void* d_out, int out_size){
    const float* lstm_repr = (const float*)d_in[0];
    const float* Wih_f     = (const float*)d_in[1];
    const float* Whh_f     = (const float*)d_in[2];
    const float* b_f       = (const float*)d_in[3];
    const float* Wih_b     = (const float*)d_in[4];
    const float* Whh_b     = (const float*)d_in[5];
    const float* b_b       = (const float*)d_in[6];
    const float* slot_emb  = (const float*)d_in[7];
    const int*   bio       = (const int*)d_in[8];
    float* out = (float*)d_out;

    cudaFuncSetAttribute(k_xg_mma, cudaFuncAttributeMaxDynamicSharedMemorySize, XSM_BYTES);
    cudaFuncSetAttribute(k_persist, cudaFuncAttributeMaxDynamicSharedMemorySize, P_BYTES);

    // order chosen so k_persist is the 4th launch (= ncu capture slot)
    k_prep<<<1024, 256>>>(Wih_f, Wih_b, b_f, b_b, Whh_f, Whh_b, slot_emb);   // includes init
    k_pack<<<BB, 64>>>(bio);
    k_xg_mma<<<dim3(16, 256), 256, XSM_BYTES>>>(lstm_repr);
    k_persist<<<NBLK, 256, P_BYTES>>>();
    k_score<<<dim3(64), 256>>>(out);
}

// round 15
// speedup vs baseline: 1.0171x; 1.0171x over previous
#include <cuda_runtime.h>
#include <cuda_bf16.h>
#include <math.h>
#include <cstdint>

// ---------------- problem constants ----------------
#define BB   64
#define TT   512
#define DD   512
#define HH   256
#define MS   64
#define ML   8
#define NST  64
#define G4   1024
#define NCOL 2048
#define NSPAN (BB*MS)        // 4096
#define NPOS  (NSPAN*ML)     // 32768
#define NBLK 148             // persistent grid (<= SM count -> all resident)

// ---------------- device scratch ----------------
__device__ int   d_nvalid;
__device__ int   d_actcount[8];
__device__ int   g_arrive;
__device__ int   d_len_g[NSPAN];
__device__ int   d_srcidx_g[NPOS];
__device__ int   d_rowidx_g[NPOS];
__device__ int   d_actlist_g[8][NSPAN];
__device__ __nv_bfloat16 d_Wh[(size_t)NCOL*DD];     // W_ih hi split [n][k]
__device__ __nv_bfloat16 d_Wl[(size_t)NCOL*DD];     // lo
__device__ __nv_bfloat16 d_Whh_h[(size_t)NCOL*HH];  // W_hh hi split [n][k] gate-interleaved
__device__ __nv_bfloat16 d_Whh_l[(size_t)NCOL*HH];  // lo
__device__ float d_bcat[NCOL];
__device__ float d_sembT[DD*NST];
__device__ float d_XG[(size_t)NPOS*NCOL];    // gate-interleaved input gates
__device__ float d_hbuf[2][NSPAN*2*HH];      // ping-pong h
__device__ float d_c[NSPAN*2*HH];
__device__ float d_pooled[NSPAN*2*HH];

__device__ __forceinline__ float sigf(float x){ return 1.0f/(1.0f+__expf(-x)); }

__device__ __forceinline__ void cp16(void* dst, const void* src){
    unsigned int d = (unsigned int)__cvta_generic_to_shared(dst);
    asm volatile("cp.async.cg.shared.global [%0], [%1], 16;\n" :: "r"(d), "l"(src));
}
__device__ __forceinline__ void cp_commit(){ asm volatile("cp.async.commit_group;\n"); }
__device__ __forceinline__ void cp_wait0(){ asm volatile("cp.async.wait_group 0;\n"); }

__device__ __forceinline__ uint32_t smem_u32(const void* p){
    uint32_t a;
    asm("{ .reg .u64 t; cvta.to.shared.u64 t, %1; cvt.u32.u64 %0, t; }" : "=r"(a) : "l"(p));
    return a;
}
__device__ __forceinline__ void ldm4(uint32_t* r, uint32_t addr){
    asm volatile("ldmatrix.sync.aligned.m8n8.x4.shared.b16 {%0,%1,%2,%3}, [%4];"
        : "=r"(r[0]),"=r"(r[1]),"=r"(r[2]),"=r"(r[3]) : "r"(addr));
}
__device__ __forceinline__ void mma16816(float* c, const uint32_t* a, const uint32_t* b){
    asm volatile("mma.sync.aligned.m16n8k16.row.col.f32.bf16.bf16.f32 "
        "{%0,%1,%2,%3}, {%4,%5,%6,%7}, {%8,%9}, {%0,%1,%2,%3};"
        : "+f"(c[0]),"+f"(c[1]),"+f"(c[2]),"+f"(c[3])
        : "r"(a[0]),"r"(a[1]),"r"(a[2]),"r"(a[3]), "r"(b[0]),"r"(b[1]));
}

// ---------------- weight prep (includes init; launched FIRST) ----------------
__global__ void k_prep(const float* __restrict__ Wih_f, const float* __restrict__ Wih_b,
                       const float* __restrict__ bf,    const float* __restrict__ bbias,
                       const float* __restrict__ Whh_f, const float* __restrict__ Whh_b,
                       const float* __restrict__ semb){
    if (blockIdx.x == 0){
        if (threadIdx.x == 0){ d_nvalid = 0; g_arrive = 0; }
        if (threadIdx.x < 8)  d_actcount[threadIdx.x] = 0;
    }
    int i = blockIdx.x*blockDim.x + threadIdx.x;
    int stride = gridDim.x*blockDim.x;
    for (int idx = i; idx < NCOL*DD; idx += stride){
        int n = idx / DD, k = idx % DD;
        int dir = n >> 10, r = n & (G4-1);
        int row = (r & 3)*HH + (r >> 2);
        float w = dir ? Wih_b[row*DD + k] : Wih_f[row*DD + k];
        __nv_bfloat16 h = __float2bfloat16(w);
        d_Wh[idx] = h;
        d_Wl[idx] = __float2bfloat16(w - __bfloat162float(h));
    }
    for (int idx = i; idx < NCOL*HH; idx += stride){
        int n = idx >> 8, k = idx & (HH-1);
        int dir = n >> 10, r = n & (G4-1);
        int row = (r & 3)*HH + (r >> 2);
        float w = dir ? Whh_b[row*HH + k] : Whh_f[row*HH + k];
        __nv_bfloat16 h = __float2bfloat16(w);
        d_Whh_h[idx] = h;
        d_Whh_l[idx] = __float2bfloat16(w - __bfloat162float(h));
    }
    for (int idx = i; idx < NCOL; idx += stride){
        int dir = idx >> 10, r = idx & (G4-1);
        int row = (r & 3)*HH + (r >> 2);
        d_bcat[idx] = dir ? bbias[row] : bf[row];
    }
    for (int idx = i; idx < DD*NST; idx += stride){
        int k = idx / NST, n = idx % NST;
        d_sembT[idx] = semb[n*DD + k];
    }
}

// ---------------- span packing (smem-staged scan) ----------------
__global__ void k_pack(const int* __restrict__ bio){
    int b = blockIdx.x;
    __shared__ int s_bio[TT];
    __shared__ int s_tok[MS][ML];
    __shared__ int s_cnt[MS];
    int tid = threadIdx.x;          // 64
    s_cnt[tid] = 0;
    for (int i = tid; i < TT; i += 64) s_bio[i] = bio[b*TT + i];
    __syncthreads();
    if (tid == 0){
        int sid = -1;
        for (int t = 0; t < TT; t++){
            int tag = s_bio[t];
            if (tag == 1) sid++;
            if ((tag == 1 || tag == 2) && sid >= 0 && sid < MS){
                int r = s_cnt[sid];
                if (r < ML) s_tok[sid][r] = t;
                s_cnt[sid] = r + 1;
            }
        }
    }
    __syncthreads();
    int s = tid;
    int len = min(s_cnt[s], ML);
    int span = b*MS + s;
    d_len_g[span] = len;
    if (len > 0){
        int base = atomicAdd(&d_nvalid, len);
        for (int r = 0; r < len; r++){
            d_srcidx_g[base+r] = b*TT + s_tok[s][r];
            d_rowidx_g[base+r] = span*ML + r;
        }
        for (int t = 1; t < ML; t++){
            if (len > t){
                int k = atomicAdd(&d_actcount[t], 1);
                d_actlist_g[t][k] = span;
            }
        }
    }
}

// ---------------- xg GEMM via mma.sync bf16 3-pass split (exact R6 kernel) ----------------
#define XPAD 40
#define ABUF (128*XPAD)      // elements per buffer

__global__ void __launch_bounds__(256) k_xg_mma(const float* __restrict__ X){
    int M = d_nvalid;
    int mBase = blockIdx.y * 128;
    if (mBase >= M) return;
    int nBase = blockIdx.x * 128;

    extern __shared__ __nv_bfloat16 sm[];
    __nv_bfloat16* Ah = sm;                  // [2][128][XPAD]
    __nv_bfloat16* Al = Ah + 2*ABUF;
    __nv_bfloat16* Bh = Al + 2*ABUF;
    __nv_bfloat16* Bl = Bh + 2*ABUF;
    int* s_sidx = (int*)(Bl + 2*ABUF);
    int* s_ridx = s_sidx + 128;

    int tid = threadIdx.x;
    if (tid < 128){
        int m = mBase + tid;
        bool v = (m < M);
        s_sidx[tid] = v ? d_srcidx_g[m]*DD : 0;
        s_ridx[tid] = v ? d_rowidx_g[m] : -1;
    }
    __syncthreads();

    int lane = tid & 31, w = tid >> 5;
    int wm = w & 3, wn = w >> 2;

    int lrow = tid >> 1, lhalf = tid & 1;
    int aoffs = lrow*XPAD + lhalf*16;
    const __nv_bfloat16* BhSrc = d_Wh + (size_t)(nBase + lrow)*DD + lhalf*16;
    const __nv_bfloat16* BlSrc = d_Wl + (size_t)(nBase + lrow)*DD + lhalf*16;
    const float* ASrc = X + s_sidx[lrow] + lhalf*16;

    int aRowOff = lane & 15;
    int aKOff   = (lane >> 4) * 8;
    int bNOff   = (lane & 7) + ((lane >> 4) << 3);
    int bKOff   = ((lane >> 3) & 1) * 8;

    uint32_t smbA_h = smem_u32(Ah), smbA_l = smem_u32(Al);
    uint32_t smbB_h = smem_u32(Bh), smbB_l = smem_u32(Bl);

    float acc[2][8][4];
    #pragma unroll
    for (int i=0;i<2;i++)
        #pragma unroll
        for (int j=0;j<8;j++)
            #pragma unroll
            for (int q=0;q<4;q++) acc[i][j][q]=0.f;

    {
        cp16(Bh + aoffs, BhSrc);       cp16(Bh + aoffs + 8, BhSrc + 8);
        cp16(Bl + aoffs, BlSrc);       cp16(Bl + aoffs + 8, BlSrc + 8);
        cp_commit();
        float4 v0 = *(const float4*)(ASrc + 0);
        float4 v1 = *(const float4*)(ASrc + 4);
        float4 v2 = *(const float4*)(ASrc + 8);
        float4 v3 = *(const float4*)(ASrc + 12);
        float fv[16] = {v0.x,v0.y,v0.z,v0.w, v1.x,v1.y,v1.z,v1.w,
                        v2.x,v2.y,v2.z,v2.w, v3.x,v3.y,v3.z,v3.w};
        __nv_bfloat16 hh[16], ll[16];
        #pragma unroll
        for (int q=0;q<16;q++){
            hh[q] = __float2bfloat16(fv[q]);
            ll[q] = __float2bfloat16(fv[q] - __bfloat162float(hh[q]));
        }
        *(uint4*)(Ah + aoffs)     = *(uint4*)(hh);
        *(uint4*)(Ah + aoffs + 8) = *(uint4*)(hh+8);
        *(uint4*)(Al + aoffs)     = *(uint4*)(ll);
        *(uint4*)(Al + aoffs + 8) = *(uint4*)(ll+8);
        cp_wait0();
        __syncthreads();
    }

    int p = 0;
    for (int kc = 0; kc < 16; kc++){
        float fv[16];
        bool more = (kc < 15);
        if (more){
            int nb = p ^ 1;
            int k0 = (kc+1)*32;
            int doffs = nb*ABUF + aoffs;
            cp16(Bh + doffs, BhSrc + k0);       cp16(Bh + doffs + 8, BhSrc + k0 + 8);
            cp16(Bl + doffs, BlSrc + k0);       cp16(Bl + doffs + 8, BlSrc + k0 + 8);
            cp_commit();
            float4 v0 = *(const float4*)(ASrc + k0 + 0);
            float4 v1 = *(const float4*)(ASrc + k0 + 4);
            float4 v2 = *(const float4*)(ASrc + k0 + 8);
            float4 v3 = *(const float4*)(ASrc + k0 + 12);
            fv[0]=v0.x; fv[1]=v0.y; fv[2]=v0.z; fv[3]=v0.w;
            fv[4]=v1.x; fv[5]=v1.y; fv[6]=v1.z; fv[7]=v1.w;
            fv[8]=v2.x; fv[9]=v2.y; fv[10]=v2.z; fv[11]=v2.w;
            fv[12]=v3.x; fv[13]=v3.y; fv[14]=v3.z; fv[15]=v3.w;
        }

        uint32_t baseAh = smbA_h + p*ABUF*2;
        uint32_t baseAl = smbA_l + p*ABUF*2;
        uint32_t baseBh = smbB_h + p*ABUF*2;
        uint32_t baseBl = smbB_l + p*ABUF*2;
        #pragma unroll
        for (int ks = 0; ks < 2; ks++){
            uint32_t ah[2][4], al[2][4];
            #pragma unroll
            for (int mt = 0; mt < 2; mt++){
                uint32_t eo = ((wm*32 + mt*16 + aRowOff)*XPAD + ks*16 + aKOff)*2;
                ldm4(ah[mt], baseAh + eo);
                ldm4(al[mt], baseAl + eo);
            }
            uint32_t bh[8][2], bl[8][2];
            #pragma unroll
            for (int g = 0; g < 4; g++){
                uint32_t eo = ((wn*64 + g*16 + bNOff)*XPAD + ks*16 + bKOff)*2;
                uint32_t r[4];
                ldm4(r, baseBh + eo);
                bh[2*g][0]=r[0]; bh[2*g][1]=r[1]; bh[2*g+1][0]=r[2]; bh[2*g+1][1]=r[3];
                ldm4(r, baseBl + eo);
                bl[2*g][0]=r[0]; bl[2*g][1]=r[1]; bl[2*g+1][0]=r[2]; bl[2*g+1][1]=r[3];
            }
            #pragma unroll
            for (int mt = 0; mt < 2; mt++)
                #pragma unroll
                for (int nt = 0; nt < 8; nt++){
                    mma16816(acc[mt][nt], ah[mt], bh[nt]);
                    mma16816(acc[mt][nt], ah[mt], bl[nt]);
                    mma16816(acc[mt][nt], al[mt], bh[nt]);
                }
        }

        if (more){
            int nb = p ^ 1;
            int doffs = nb*ABUF + aoffs;
            __nv_bfloat16 hh[16], ll[16];
            #pragma unroll
            for (int q=0;q<16;q++){
                hh[q] = __float2bfloat16(fv[q]);
                ll[q] = __float2bfloat16(fv[q] - __bfloat162float(hh[q]));
            }
            *(uint4*)(Ah + doffs)     = *(uint4*)(hh);
            *(uint4*)(Ah + doffs + 8) = *(uint4*)(hh+8);
            *(uint4*)(Al + doffs)     = *(uint4*)(ll);
            *(uint4*)(Al + doffs + 8) = *(uint4*)(ll+8);
            cp_wait0();
        }
        __syncthreads();
        p ^= 1;
    }

    #pragma unroll
    for (int mt = 0; mt < 2; mt++){
        int rl0 = wm*32 + mt*16 + (lane >> 2);
        #pragma unroll
        for (int half = 0; half < 2; half++){
            int rl = rl0 + half*8;
            int grow = s_ridx[rl];
            if (grow < 0) continue;
            float* dst = d_XG + (size_t)grow*NCOL + nBase;
            #pragma unroll
            for (int nt = 0; nt < 8; nt++){
                int col = wn*64 + nt*8 + (lane & 3)*2;
                float2 b2 = *(const float2*)(d_bcat + nBase + col);
                float2 o;
                o.x = acc[mt][nt][half*2+0] + b2.x;
                o.y = acc[mt][nt][half*2+1] + b2.y;
                *(float2*)(dst + col) = o;
            }
        }
    }
}
#define XSM_BYTES (8*ABUF*2 + 256*4)

// ---------------- persistent recurrence: B-resident tensor-core step GEMMs ----------------
// B slice (128 gate-cols x K=256, hi+lo) stays in smem across all m-subtiles of a
// column-tile; tiles ordered ct-major with contiguous per-block ranges for reuse.
// Row stride 528 B (264 bf16): ldmatrix bank starts 4r mod 32 -> conflict-free.
#define PSTRIDE 528
#define P2_BH   0                    // 128*528 = 67584
#define P2_BL   67584
#define P2_AH   135168               // 32*528 = 16896
#define P2_AL   152064
#define P2_CS   168960               // [32][132] float = 16896
#define P2_SPN  185856
#define P2_AOFF 185984
#define P2_SLEN 186112
#define P2_BYTES 186240

__global__ void __launch_bounds__(256) k_persist(){
    extern __shared__ char psm[];
    float* Cs = (float*)(psm + P2_CS);
    int* spn  = (int*)(psm + P2_SPN);
    int* aoff = (int*)(psm + P2_AOFF);
    int* slen = (int*)(psm + P2_SLEN);
    uint32_t smb = smem_u32(psm);
    int tid = threadIdx.x, bid = blockIdx.x;
    int lane = tid & 31, w = tid >> 5;
    int wm = w & 1, wn = w >> 1;                 // 2 m-groups x 4 n-groups

    // ---- phase 0: step 0 pointwise ----
    for (int idx = bid*256 + tid; idx < NSPAN*2*HH; idx += NBLK*256){
        int span = idx >> 9;
        int rem  = idx & 511;
        int dir  = rem >> 8;
        int j    = rem & 255;
        int len  = d_len_g[span];
        if (len == 0){
            d_hbuf[0][idx] = 0.f; d_c[idx] = 0.f; d_pooled[idx] = 0.f;
        } else {
            int rank = dir ? (len-1) : 0;
            float4 g = *(const float4*)(d_XG + (size_t)(span*ML + rank)*NCOL + dir*G4 + j*4);
            float c = sigf(g.x) * tanhf(g.z);
            float h = sigf(g.w) * tanhf(c);
            d_c[idx] = c; d_hbuf[0][idx] = h; d_pooled[idx] = h;
        }
    }

    int aRowOff = lane & 15;
    int aKOff   = (lane >> 4) * 8;
    int bNOff   = (lane & 7) + ((lane >> 4) << 3);
    int bKOff   = ((lane >> 3) & 1) * 8;
    int arow = tid >> 3, aseg = tid & 7;         // A loader: row 0..31, 32 floats each

    for (int t = 1; t < ML; t++){
        // ---- global epoch barrier #t ----
        __syncthreads();
        if (tid == 0){
            __threadfence();
            atomicAdd(&g_arrive, 1);
            while (atomicAdd(&g_arrive, 0) < t*NBLK) { }
        }
        __syncthreads();

        int cnt = d_actcount[t];
        if (cnt <= 0) continue;
        const float* __restrict__ h_r = d_hbuf[(t-1)&1];
        float* __restrict__ h_w = d_hbuf[t&1];
        int nmt  = (cnt + 31) >> 5;
        int ntot = nmt * 16;
        int lenb = (ntot + NBLK - 1) / NBLK;
        int tstart = bid * lenb;
        int tend   = min(tstart + lenb, ntot);
        int cur_ct = -1;

        for (int tile = tstart; tile < tend; tile++){
            int ct  = tile / nmt;
            int mt  = tile - ct*nmt;
            int dir = ct >> 3;
            int nb  = (ct & 7) * 128;
            bool loadB = (ct != cur_ct);
            cur_ct = ct;

            __syncthreads();                      // protect spn/A/Cs from prev iter
            if (tid < 32){
                int m = mt*32 + tid;
                int span = (m < cnt) ? d_actlist_g[t][m] : -1;
                spn[tid] = span;
                int s0 = (span >= 0) ? span : 0;
                aoff[tid] = (s0*2 + dir)*HH;
                slen[tid] = d_len_g[s0];
            }
            __syncthreads();

            if (loadB){
                const __nv_bfloat16* WhhH = d_Whh_h + (size_t)(dir*G4 + nb)*HH;
                const __nv_bfloat16* WhhL = d_Whh_l + (size_t)(dir*G4 + nb)*HH;
                #pragma unroll
                for (int li = 0; li < 16; li++){
                    int lin = tid + li*256;
                    int row = lin >> 5, seg = lin & 31;
                    cp16(psm + P2_BH + row*PSTRIDE + seg*16, WhhH + (size_t)row*HH + seg*8);
                    cp16(psm + P2_BL + row*PSTRIDE + seg*16, WhhL + (size_t)row*HH + seg*8);
                }
                cp_commit();
            }

            // ---- A load + split (full K=256 at once) ----
            {
                const float* src = h_r + aoff[arow] + aseg*32;
                #pragma unroll
                for (int u = 0; u < 4; u++){
                    float4 a0 = *(const float4*)(src + u*8);
                    float4 a1 = *(const float4*)(src + u*8 + 4);
                    __nv_bfloat162 h0 = __floats2bfloat162_rn(a0.x, a0.y);
                    __nv_bfloat162 h1 = __floats2bfloat162_rn(a0.z, a0.w);
                    __nv_bfloat162 h2 = __floats2bfloat162_rn(a1.x, a1.y);
                    __nv_bfloat162 h3 = __floats2bfloat162_rn(a1.z, a1.w);
                    __nv_bfloat162 l0 = __floats2bfloat162_rn(a0.x - __bfloat162float(h0.x), a0.y - __bfloat162float(h0.y));
                    __nv_bfloat162 l1 = __floats2bfloat162_rn(a0.z - __bfloat162float(h1.x), a0.w - __bfloat162float(h1.y));
                    __nv_bfloat162 l2 = __floats2bfloat162_rn(a1.x - __bfloat162float(h2.x), a1.y - __bfloat162float(h2.y));
                    __nv_bfloat162 l3 = __floats2bfloat162_rn(a1.z - __bfloat162float(h3.x), a1.w - __bfloat162float(h3.y));
                    uint4 uh, ul;
                    uh.x = *(uint32_t*)&h0; uh.y = *(uint32_t*)&h1; uh.z = *(uint32_t*)&h2; uh.w = *(uint32_t*)&h3;
                    ul.x = *(uint32_t*)&l0; ul.y = *(uint32_t*)&l1; ul.z = *(uint32_t*)&l2; ul.w = *(uint32_t*)&l3;
                    int off = arow*PSTRIDE + (aseg*32 + u*8)*2;
                    *(uint4*)(psm + P2_AH + off) = uh;
                    *(uint4*)(psm + P2_AL + off) = ul;
                }
            }
            if (loadB) cp_wait0();
            __syncthreads();

            // ---- MMA: 16 ks steps over resident A/B ----
            float acc[4][4];
            #pragma unroll
            for (int i=0;i<4;i++)
                #pragma unroll
                for (int q=0;q<4;q++) acc[i][q]=0.f;

            #pragma unroll
            for (int ks = 0; ks < 16; ks++){
                uint32_t ah[4], al[4];
                uint32_t eoA = (wm*16 + aRowOff)*PSTRIDE + (ks*16 + aKOff)*2;
                ldm4(ah, smb + P2_AH + eoA);
                ldm4(al, smb + P2_AL + eoA);
                uint32_t bh[4][2], bl[4][2];
                #pragma unroll
                for (int g = 0; g < 2; g++){
                    uint32_t eo = (wn*32 + g*16 + bNOff)*PSTRIDE + (ks*16 + bKOff)*2;
                    uint32_t r[4];
                    ldm4(r, smb + P2_BH + eo);
                    bh[2*g][0]=r[0]; bh[2*g][1]=r[1]; bh[2*g+1][0]=r[2]; bh[2*g+1][1]=r[3];
                    ldm4(r, smb + P2_BL + eo);
                    bl[2*g][0]=r[0]; bl[2*g][1]=r[1]; bl[2*g+1][0]=r[2]; bl[2*g+1][1]=r[3];
                }
                #pragma unroll
                for (int nt = 0; nt < 4; nt++){
                    mma16816(acc[nt], ah, bh[nt]);
                    mma16816(acc[nt], ah, bl[nt]);
                    mma16816(acc[nt], al, bh[nt]);
                }
            }

            // ---- stage accs to Cs [32][132] ----
            __syncthreads();
            #pragma unroll
            for (int nt = 0; nt < 4; nt++){
                int col = wn*32 + nt*8 + (lane & 3)*2;
                int r0  = wm*16 + (lane >> 2);
                Cs[r0*132 + col]     = acc[nt][0];
                Cs[r0*132 + col + 1] = acc[nt][1];
                Cs[(r0+8)*132 + col]     = acc[nt][2];
                Cs[(r0+8)*132 + col + 1] = acc[nt][3];
            }
            __syncthreads();

            // ---- LSTM epilogue: each thread 4 (row,j) cells ----
            #pragma unroll
            for (int e = 0; e < 4; e++){
                int idx = tid + e*256;
                int row = idx >> 5, jj = idx & 31;
                int span = spn[row];
                if (span < 0) continue;
                float4 g4 = *(const float4*)&Cs[row*132 + jj*4];
                int rank = dir ? (slen[row]-1-t) : t;
                int j0 = (nb >> 2) + jj;
                float4 xg = *(const float4*)(d_XG + (size_t)(span*ML + rank)*NCOL + dir*G4 + j0*4);
                int he = (span*2 + dir)*HH + j0;
                float c = d_c[he];
                float gi = g4.x+xg.x, gf = g4.y+xg.y, gg = g4.z+xg.z, go = g4.w+xg.w;
                c = sigf(gf)*c + sigf(gi)*tanhf(gg);
                float h = sigf(go)*tanhf(c);
                d_c[he] = c;
                h_w[he] = h;
                d_pooled[he] += h;
            }
        }
    }
}

// ---------------- scoring GEMM: pooled [4096,512] x sembT [512,64] ----------------
__global__ void k_score(float* __restrict__ out){
    const int BM=64, BN=64, BK=16;
    int mBase = blockIdx.x * BM;
    __shared__ float As[BK][BM];
    __shared__ float Bs[BK][BN];
    int tid = threadIdx.x;
    float acc[4][4];
    #pragma unroll
    for (int i=0;i<4;i++)
        #pragma unroll
        for (int j=0;j<4;j++) acc[i][j]=0.f;
    int ty = tid >> 4, tx = tid & 15;
    for (int k0 = 0; k0 < DD; k0 += BK){
        {
            int row = tid >> 2;
            int kq  = (tid & 3) * 4;
            float4 v = *reinterpret_cast<const float4*>(d_pooled + (size_t)(mBase+row)*DD + k0 + kq);
            As[kq+0][row]=v.x; As[kq+1][row]=v.y; As[kq+2][row]=v.z; As[kq+3][row]=v.w;
        }
        {
            int kb = tid >> 4;
            int nq = (tid & 15) * 4;
            *reinterpret_cast<float4*>(&Bs[kb][nq]) =
                *reinterpret_cast<const float4*>(d_sembT + (size_t)(k0+kb)*NST + nq);
        }
        __syncthreads();
        #pragma unroll
        for (int kk=0; kk<BK; kk++){
            float a[4], b[4];
            *reinterpret_cast<float4*>(a) = *reinterpret_cast<float4*>(&As[kk][ty*4]);
            *reinterpret_cast<float4*>(b) = *reinterpret_cast<float4*>(&Bs[kk][tx*4]);
            #pragma unroll
            for (int i=0;i<4;i++)
                #pragma unroll
                for (int j=0;j<4;j++) acc[i][j] += a[i]*b[j];
        }
        __syncthreads();
    }
    #pragma unroll
    for (int i=0;i<4;i++){
        int r = mBase + ty*4 + i;
        #pragma unroll
        for (int j=0;j<4;j++)
            out[(size_t)r*NST + tx*4 + j] = acc[i][j];
    }
}

// ---------------- launch ----------------
extern "C" void kernel_launch(void* const* d_in, const int* in_sizes, int n_in,
                              void* d_out, int out_size){
    const float* lstm_repr = (const float*)d_in[0];
    const float* Wih_f     = (const float*)d_in[1];
    const float* Whh_f     = (const float*)d_in[2];
    const float* b_f       = (const float*)d_in[3];
    const float* Wih_b     = (const float*)d_in[4];
    const float* Whh_b     = (const float*)d_in[5];
    const float* b_b       = (const float*)d_in[6];
    const float* slot_emb  = (const float*)d_in[7];
    const int*   bio       = (const int*)d_in[8];
    float* out = (float*)d_out;

    cudaFuncSetAttribute(k_xg_mma, cudaFuncAttributeMaxDynamicSharedMemorySize, XSM_BYTES);
    cudaFuncSetAttribute(k_persist, cudaFuncAttributeMaxDynamicSharedMemorySize, P2_BYTES);

    // order chosen so k_persist is the 4th launch (= ncu capture slot)
    k_prep<<<1024, 256>>>(Wih_f, Wih_b, b_f, b_b, Whh_f, Whh_b, slot_emb);   // includes init
    k_pack<<<BB, 64>>>(bio);
    k_xg_mma<<<dim3(16, 256), 256, XSM_BYTES>>>(lstm_repr);
    k_persist<<<NBLK, 256, P2_BYTES>>>();
    k_score<<<dim3(64), 256>>>(out);
}

// round 16
// speedup vs baseline: 1.5133x; 1.4879x over previous
#include <cuda_runtime.h>
#include <cuda_bf16.h>
#include <math.h>
#include <cstdint>

// ---------------- problem constants ----------------
#define BB   64
#define TT   512
#define DD   512
#define HH   256
#define MS   64
#define ML   8
#define NST  64
#define G4   1024
#define NCOL 2048
#define NSPAN (BB*MS)        // 4096
#define NPOS  (NSPAN*ML)     // 32768
#define NBLK 148             // persistent grid (<= SM count -> all resident)

// ---------------- device scratch ----------------
__device__ int   d_nvalid;
__device__ int   d_actcount[8];
__device__ int   g_arrive;
__device__ int   d_len_g[NSPAN];
__device__ int   d_srcidx_g[NPOS];
__device__ int   d_rowidx_g[NPOS];
__device__ int   d_actlist_g[8][NSPAN];
__device__ __nv_bfloat16 d_Wh[(size_t)NCOL*DD];     // W_ih hi split [n][k]
__device__ __nv_bfloat16 d_Wl[(size_t)NCOL*DD];     // lo
__device__ __nv_bfloat16 d_Whh_h[(size_t)NCOL*HH];  // W_hh hi split [n][k] gate-interleaved
__device__ __nv_bfloat16 d_Whh_l[(size_t)NCOL*HH];  // lo
__device__ float d_bcat[NCOL];
__device__ float d_sembT[DD*NST];
__device__ float d_XG[(size_t)NPOS*NCOL];    // gate-interleaved input gates
__device__ float d_hbuf[2][NSPAN*2*HH];      // ping-pong h
__device__ float d_c[NSPAN*2*HH];
__device__ float d_pooled[NSPAN*2*HH];

__device__ __forceinline__ float sigf(float x){ return 1.0f/(1.0f+__expf(-x)); }

__device__ __forceinline__ void cp16(void* dst, const void* src){
    unsigned int d = (unsigned int)__cvta_generic_to_shared(dst);
    asm volatile("cp.async.cg.shared.global [%0], [%1], 16;\n" :: "r"(d), "l"(src));
}
__device__ __forceinline__ void cp_commit(){ asm volatile("cp.async.commit_group;\n"); }
__device__ __forceinline__ void cp_wait0(){ asm volatile("cp.async.wait_group 0;\n"); }

__device__ __forceinline__ uint32_t smem_u32(const void* p){
    uint32_t a;
    asm("{ .reg .u64 t; cvta.to.shared.u64 t, %1; cvt.u32.u64 %0, t; }" : "=r"(a) : "l"(p));
    return a;
}
__device__ __forceinline__ void ldm4(uint32_t* r, uint32_t addr){
    asm volatile("ldmatrix.sync.aligned.m8n8.x4.shared.b16 {%0,%1,%2,%3}, [%4];"
        : "=r"(r[0]),"=r"(r[1]),"=r"(r[2]),"=r"(r[3]) : "r"(addr));
}
__device__ __forceinline__ void mma16816(float* c, const uint32_t* a, const uint32_t* b){
    asm volatile("mma.sync.aligned.m16n8k16.row.col.f32.bf16.bf16.f32 "
        "{%0,%1,%2,%3}, {%4,%5,%6,%7}, {%8,%9}, {%0,%1,%2,%3};"
        : "+f"(c[0]),"+f"(c[1]),"+f"(c[2]),"+f"(c[3])
        : "r"(a[0]),"r"(a[1]),"r"(a[2]),"r"(a[3]), "r"(b[0]),"r"(b[1]));
}
__device__ __forceinline__ int ld_acq(const int* p){
    int v;
    asm volatile("ld.acquire.gpu.b32 %0, [%1];" : "=r"(v) : "l"(p) : "memory");
    return v;
}

// ---------------- weight prep (includes init; launched FIRST) ----------------
__global__ void k_prep(const float* __restrict__ Wih_f, const float* __restrict__ Wih_b,
                       const float* __restrict__ bf,    const float* __restrict__ bbias,
                       const float* __restrict__ Whh_f, const float* __restrict__ Whh_b,
                       const float* __restrict__ semb){
    if (blockIdx.x == 0){
        if (threadIdx.x == 0){ d_nvalid = 0; g_arrive = 0; }
        if (threadIdx.x < 8)  d_actcount[threadIdx.x] = 0;
    }
    int i = blockIdx.x*blockDim.x + threadIdx.x;
    int stride = gridDim.x*blockDim.x;
    for (int idx = i; idx < NCOL*DD; idx += stride){
        int n = idx / DD, k = idx % DD;
        int dir = n >> 10, r = n & (G4-1);
        int row = (r & 3)*HH + (r >> 2);
        float w = dir ? Wih_b[row*DD + k] : Wih_f[row*DD + k];
        __nv_bfloat16 h = __float2bfloat16(w);
        d_Wh[idx] = h;
        d_Wl[idx] = __float2bfloat16(w - __bfloat162float(h));
    }
    for (int idx = i; idx < NCOL*HH; idx += stride){
        int n = idx >> 8, k = idx & (HH-1);
        int dir = n >> 10, r = n & (G4-1);
        int row = (r & 3)*HH + (r >> 2);
        float w = dir ? Whh_b[row*HH + k] : Whh_f[row*HH + k];
        __nv_bfloat16 h = __float2bfloat16(w);
        d_Whh_h[idx] = h;
        d_Whh_l[idx] = __float2bfloat16(w - __bfloat162float(h));
    }
    for (int idx = i; idx < NCOL; idx += stride){
        int dir = idx >> 10, r = idx & (G4-1);
        int row = (r & 3)*HH + (r >> 2);
        d_bcat[idx] = dir ? bbias[row] : bf[row];
    }
    for (int idx = i; idx < DD*NST; idx += stride){
        int k = idx / NST, n = idx % NST;
        d_sembT[idx] = semb[n*DD + k];
    }
}

// ---------------- span packing (smem-staged scan) ----------------
__global__ void k_pack(const int* __restrict__ bio){
    int b = blockIdx.x;
    __shared__ int s_bio[TT];
    __shared__ int s_tok[MS][ML];
    __shared__ int s_cnt[MS];
    int tid = threadIdx.x;          // 64
    s_cnt[tid] = 0;
    for (int i = tid; i < TT; i += 64) s_bio[i] = bio[b*TT + i];
    __syncthreads();
    if (tid == 0){
        int sid = -1;
        for (int t = 0; t < TT; t++){
            int tag = s_bio[t];
            if (tag == 1) sid++;
            if ((tag == 1 || tag == 2) && sid >= 0 && sid < MS){
                int r = s_cnt[sid];
                if (r < ML) s_tok[sid][r] = t;
                s_cnt[sid] = r + 1;
            }
        }
    }
    __syncthreads();
    int s = tid;
    int len = min(s_cnt[s], ML);
    int span = b*MS + s;
    d_len_g[span] = len;
    if (len > 0){
        int base = atomicAdd(&d_nvalid, len);
        for (int r = 0; r < len; r++){
            d_srcidx_g[base+r] = b*TT + s_tok[s][r];
            d_rowidx_g[base+r] = span*ML + r;
        }
        for (int t = 1; t < ML; t++){
            if (len > t){
                int k = atomicAdd(&d_actcount[t], 1);
                d_actlist_g[t][k] = span;
            }
        }
    }
}

// ---------------- xg GEMM via mma.sync bf16 3-pass split (exact R6 kernel) ----------------
#define XPAD 40
#define ABUF (128*XPAD)      // elements per buffer

__global__ void __launch_bounds__(256) k_xg_mma(const float* __restrict__ X){
    int M = d_nvalid;
    int mBase = blockIdx.y * 128;
    if (mBase >= M) return;
    int nBase = blockIdx.x * 128;

    extern __shared__ __nv_bfloat16 sm[];
    __nv_bfloat16* Ah = sm;                  // [2][128][XPAD]
    __nv_bfloat16* Al = Ah + 2*ABUF;
    __nv_bfloat16* Bh = Al + 2*ABUF;
    __nv_bfloat16* Bl = Bh + 2*ABUF;
    int* s_sidx = (int*)(Bl + 2*ABUF);
    int* s_ridx = s_sidx + 128;

    int tid = threadIdx.x;
    if (tid < 128){
        int m = mBase + tid;
        bool v = (m < M);
        s_sidx[tid] = v ? d_srcidx_g[m]*DD : 0;
        s_ridx[tid] = v ? d_rowidx_g[m] : -1;
    }
    __syncthreads();

    int lane = tid & 31, w = tid >> 5;
    int wm = w & 3, wn = w >> 2;

    int lrow = tid >> 1, lhalf = tid & 1;
    int aoffs = lrow*XPAD + lhalf*16;
    const __nv_bfloat16* BhSrc = d_Wh + (size_t)(nBase + lrow)*DD + lhalf*16;
    const __nv_bfloat16* BlSrc = d_Wl + (size_t)(nBase + lrow)*DD + lhalf*16;
    const float* ASrc = X + s_sidx[lrow] + lhalf*16;

    int aRowOff = lane & 15;
    int aKOff   = (lane >> 4) * 8;
    int bNOff   = (lane & 7) + ((lane >> 4) << 3);
    int bKOff   = ((lane >> 3) & 1) * 8;

    uint32_t smbA_h = smem_u32(Ah), smbA_l = smem_u32(Al);
    uint32_t smbB_h = smem_u32(Bh), smbB_l = smem_u32(Bl);

    float acc[2][8][4];
    #pragma unroll
    for (int i=0;i<2;i++)
        #pragma unroll
        for (int j=0;j<8;j++)
            #pragma unroll
            for (int q=0;q<4;q++) acc[i][j][q]=0.f;

    {
        cp16(Bh + aoffs, BhSrc);       cp16(Bh + aoffs + 8, BhSrc + 8);
        cp16(Bl + aoffs, BlSrc);       cp16(Bl + aoffs + 8, BlSrc + 8);
        cp_commit();
        float4 v0 = *(const float4*)(ASrc + 0);
        float4 v1 = *(const float4*)(ASrc + 4);
        float4 v2 = *(const float4*)(ASrc + 8);
        float4 v3 = *(const float4*)(ASrc + 12);
        float fv[16] = {v0.x,v0.y,v0.z,v0.w, v1.x,v1.y,v1.z,v1.w,
                        v2.x,v2.y,v2.z,v2.w, v3.x,v3.y,v3.z,v3.w};
        __nv_bfloat16 hh[16], ll[16];
        #pragma unroll
        for (int q=0;q<16;q++){
            hh[q] = __float2bfloat16(fv[q]);
            ll[q] = __float2bfloat16(fv[q] - __bfloat162float(hh[q]));
        }
        *(uint4*)(Ah + aoffs)     = *(uint4*)(hh);
        *(uint4*)(Ah + aoffs + 8) = *(uint4*)(hh+8);
        *(uint4*)(Al + aoffs)     = *(uint4*)(ll);
        *(uint4*)(Al + aoffs + 8) = *(uint4*)(ll+8);
        cp_wait0();
        __syncthreads();
    }

    int p = 0;
    for (int kc = 0; kc < 16; kc++){
        float fv[16];
        bool more = (kc < 15);
        if (more){
            int nb = p ^ 1;
            int k0 = (kc+1)*32;
            int doffs = nb*ABUF + aoffs;
            cp16(Bh + doffs, BhSrc + k0);       cp16(Bh + doffs + 8, BhSrc + k0 + 8);
            cp16(Bl + doffs, BlSrc + k0);       cp16(Bl + doffs + 8, BlSrc + k0 + 8);
            cp_commit();
            float4 v0 = *(const float4*)(ASrc + k0 + 0);
            float4 v1 = *(const float4*)(ASrc + k0 + 4);
            float4 v2 = *(const float4*)(ASrc + k0 + 8);
            float4 v3 = *(const float4*)(ASrc + k0 + 12);
            fv[0]=v0.x; fv[1]=v0.y; fv[2]=v0.z; fv[3]=v0.w;
            fv[4]=v1.x; fv[5]=v1.y; fv[6]=v1.z; fv[7]=v1.w;
            fv[8]=v2.x; fv[9]=v2.y; fv[10]=v2.z; fv[11]=v2.w;
            fv[12]=v3.x; fv[13]=v3.y; fv[14]=v3.z; fv[15]=v3.w;
        }

        uint32_t baseAh = smbA_h + p*ABUF*2;
        uint32_t baseAl = smbA_l + p*ABUF*2;
        uint32_t baseBh = smbB_h + p*ABUF*2;
        uint32_t baseBl = smbB_l + p*ABUF*2;
        #pragma unroll
        for (int ks = 0; ks < 2; ks++){
            uint32_t ah[2][4], al[2][4];
            #pragma unroll
            for (int mt = 0; mt < 2; mt++){
                uint32_t eo = ((wm*32 + mt*16 + aRowOff)*XPAD + ks*16 + aKOff)*2;
                ldm4(ah[mt], baseAh + eo);
                ldm4(al[mt], baseAl + eo);
            }
            uint32_t bh[8][2], bl[8][2];
            #pragma unroll
            for (int g = 0; g < 4; g++){
                uint32_t eo = ((wn*64 + g*16 + bNOff)*XPAD + ks*16 + bKOff)*2;
                uint32_t r[4];
                ldm4(r, baseBh + eo);
                bh[2*g][0]=r[0]; bh[2*g][1]=r[1]; bh[2*g+1][0]=r[2]; bh[2*g+1][1]=r[3];
                ldm4(r, baseBl + eo);
                bl[2*g][0]=r[0]; bl[2*g][1]=r[1]; bl[2*g+1][0]=r[2]; bl[2*g+1][1]=r[3];
            }
            #pragma unroll
            for (int mt = 0; mt < 2; mt++)
                #pragma unroll
                for (int nt = 0; nt < 8; nt++){
                    mma16816(acc[mt][nt], ah[mt], bh[nt]);
                    mma16816(acc[mt][nt], ah[mt], bl[nt]);
                    mma16816(acc[mt][nt], al[mt], bh[nt]);
                }
        }

        if (more){
            int nb = p ^ 1;
            int doffs = nb*ABUF + aoffs;
            __nv_bfloat16 hh[16], ll[16];
            #pragma unroll
            for (int q=0;q<16;q++){
                hh[q] = __float2bfloat16(fv[q]);
                ll[q] = __float2bfloat16(fv[q] - __bfloat162float(hh[q]));
            }
            *(uint4*)(Ah + doffs)     = *(uint4*)(hh);
            *(uint4*)(Ah + doffs + 8) = *(uint4*)(hh+8);
            *(uint4*)(Al + doffs)     = *(uint4*)(ll);
            *(uint4*)(Al + doffs + 8) = *(uint4*)(ll+8);
            cp_wait0();
        }
        __syncthreads();
        p ^= 1;
    }

    #pragma unroll
    for (int mt = 0; mt < 2; mt++){
        int rl0 = wm*32 + mt*16 + (lane >> 2);
        #pragma unroll
        for (int half = 0; half < 2; half++){
            int rl = rl0 + half*8;
            int grow = s_ridx[rl];
            if (grow < 0) continue;
            float* dst = d_XG + (size_t)grow*NCOL + nBase;
            #pragma unroll
            for (int nt = 0; nt < 8; nt++){
                int col = wn*64 + nt*8 + (lane & 3)*2;
                float2 b2 = *(const float2*)(d_bcat + nBase + col);
                float2 o;
                o.x = acc[mt][nt][half*2+0] + b2.x;
                o.y = acc[mt][nt][half*2+1] + b2.y;
                *(float2*)(dst + col) = o;
            }
        }
    }
}
#define XSM_BYTES (8*ABUF*2 + 256*4)

// ---------------- persistent recurrence (R13 structure + MLP batching) ----------------
// tile: BM=32 spans x BN=128 gate-cols x K=256, K-chunk 32, bf16 hi/lo 3-pass mma.
#define P_AH 0                       // [2][32][40] bf16 = 5120
#define P_AL 5120
#define P_BH 10240                   // [2][128][40] bf16 = 20480
#define P_BL 30720
#define P_CS 51200                   // [32][132] float = 16896
#define P_SPN 68096
#define P_AOFF 68224
#define P_SLEN 68352
#define P_BYTES 68480
#define P_ABUFB 2560                 // A per-buffer bytes (32*80)
#define P_BBUFB 10240                // B per-buffer bytes (128*80)

__global__ void __launch_bounds__(256) k_persist(){
    extern __shared__ char psm[];
    float* Cs = (float*)(psm + P_CS);            // [32][132]
    int* spn  = (int*)(psm + P_SPN);
    int* aoff = (int*)(psm + P_AOFF);
    int* slen = (int*)(psm + P_SLEN);
    uint32_t smb = smem_u32(psm);
    int tid = threadIdx.x, bid = blockIdx.x;
    int lane = tid & 31, w = tid >> 5;
    int wm = w & 1, wn = w >> 1;                 // 2 m-groups x 4 n-groups

    // ---- phase 0: step 0 pointwise, 4-way batched loads (MLP) ----
    {
        const int TOT = NSPAN*2*HH;
        const int stride = NBLK*256;
        for (int base = bid*256 + tid; base < TOT; base += 4*stride){
            int lenA[4]; bool vA[4]; float4 gA[4];
            #pragma unroll
            for (int r = 0; r < 4; r++){
                int idx = base + r*stride;
                vA[r] = (idx < TOT);
                lenA[r] = vA[r] ? d_len_g[idx >> 9] : 0;
            }
            #pragma unroll
            for (int r = 0; r < 4; r++){
                if (!vA[r] || lenA[r] == 0) continue;
                int idx = base + r*stride;
                int rem = idx & 511;
                int dir = rem >> 8, j = rem & 255, span = idx >> 9;
                int rank = dir ? (lenA[r]-1) : 0;
                gA[r] = *(const float4*)(d_XG + (size_t)(span*ML + rank)*NCOL + dir*G4 + j*4);
            }
            #pragma unroll
            for (int r = 0; r < 4; r++){
                if (!vA[r]) continue;
                int idx = base + r*stride;
                if (lenA[r] == 0){
                    d_hbuf[0][idx] = 0.f; d_c[idx] = 0.f; d_pooled[idx] = 0.f;
                } else {
                    float c = sigf(gA[r].x) * tanhf(gA[r].z);
                    float h = sigf(gA[r].w) * tanhf(c);
                    d_c[idx] = c; d_hbuf[0][idx] = h; d_pooled[idx] = h;
                }
            }
        }
    }

    int aRowOff = lane & 15;
    int aKOff   = (lane >> 4) * 8;
    int bNOff   = (lane & 7) + ((lane >> 4) << 3);
    int bKOff   = ((lane >> 3) & 1) * 8;
    int arow = tid >> 3, akq = (tid & 7) * 4;    // A loader: row 0..31, 4 floats each

    for (int t = 1; t < ML; t++){
        // ---- global epoch barrier #t (release-arrive, acquire-poll) ----
        __syncthreads();
        if (tid == 0){
            __threadfence();
            atomicAdd(&g_arrive, 1);
            while (ld_acq(&g_arrive) < t*NBLK) { }
        }
        __syncthreads();

        int cnt = d_actcount[t];
        if (cnt <= 0) continue;
        const float* __restrict__ h_r = d_hbuf[(t-1)&1];
        float* __restrict__ h_w = d_hbuf[t&1];
        int nmt  = (cnt + 31) >> 5;
        int ntot = nmt * 16;

        for (int tile = bid; tile < ntot; tile += NBLK){
            int mt  = tile >> 4;
            int ct  = tile & 15;
            int dir = ct >> 3;
            int nb  = (ct & 7) * 128;

            __syncthreads();          // previous tile's smem fully consumed
            if (tid < 32){
                int m = mt*32 + tid;
                int span = (m < cnt) ? d_actlist_g[t][m] : -1;
                spn[tid] = span;
                int s0 = (span >= 0) ? span : 0;
                aoff[tid] = (s0*2 + dir)*HH;
                slen[tid] = d_len_g[s0];
            }
            __syncthreads();

            const __nv_bfloat16* WhhH = d_Whh_h + (size_t)(dir*G4 + nb)*HH;
            const __nv_bfloat16* WhhL = d_Whh_l + (size_t)(dir*G4 + nb)*HH;

            // ---- prologue: chunk 0 into buffer 0 ----
            {
                #pragma unroll
                for (int li = 0; li < 2; li++){
                    int lin = tid + li*256;
                    int row = lin >> 2, seg = lin & 3;
                    cp16(psm + P_BH + row*80 + seg*16, WhhH + (size_t)row*HH + seg*8);
                    cp16(psm + P_BL + row*80 + seg*16, WhhL + (size_t)row*HH + seg*8);
                }
                cp_commit();
                float4 av = *(const float4*)(h_r + aoff[arow] + akq);
                __nv_bfloat162 h0 = __floats2bfloat162_rn(av.x, av.y);
                __nv_bfloat162 h1 = __floats2bfloat162_rn(av.z, av.w);
                __nv_bfloat162 l0 = __floats2bfloat162_rn(av.x - __bfloat162float(h0.x), av.y - __bfloat162float(h0.y));
                __nv_bfloat162 l1 = __floats2bfloat162_rn(av.z - __bfloat162float(h1.x), av.w - __bfloat162float(h1.y));
                uint2 uh, ul;
                uh.x = *(uint32_t*)&h0; uh.y = *(uint32_t*)&h1;
                ul.x = *(uint32_t*)&l0; ul.y = *(uint32_t*)&l1;
                *(uint2*)(psm + P_AH + arow*80 + akq*2) = uh;
                *(uint2*)(psm + P_AL + arow*80 + akq*2) = ul;
                cp_wait0();
                __syncthreads();
            }

            float acc[4][4];
            #pragma unroll
            for (int i=0;i<4;i++)
                #pragma unroll
                for (int q=0;q<4;q++) acc[i][q]=0.f;

            int p = 0;
            for (int kc = 0; kc < 8; kc++){
                bool more = (kc < 7);
                if (more){
                    int nbuf = p ^ 1;
                    int k0 = (kc+1)*32;
                    #pragma unroll
                    for (int li = 0; li < 2; li++){
                        int lin = tid + li*256;
                        int row = lin >> 2, seg = lin & 3;
                        cp16(psm + P_BH + nbuf*P_BBUFB + row*80 + seg*16, WhhH + (size_t)row*HH + k0 + seg*8);
                        cp16(psm + P_BL + nbuf*P_BBUFB + row*80 + seg*16, WhhL + (size_t)row*HH + k0 + seg*8);
                    }
                    cp_commit();
                    float4 av = *(const float4*)(h_r + aoff[arow] + k0 + akq);
                    __nv_bfloat162 h0 = __floats2bfloat162_rn(av.x, av.y);
                    __nv_bfloat162 h1 = __floats2bfloat162_rn(av.z, av.w);
                    __nv_bfloat162 l0 = __floats2bfloat162_rn(av.x - __bfloat162float(h0.x), av.y - __bfloat162float(h0.y));
                    __nv_bfloat162 l1 = __floats2bfloat162_rn(av.z - __bfloat162float(h1.x), av.w - __bfloat162float(h1.y));
                    uint2 uh, ul;
                    uh.x = *(uint32_t*)&h0; uh.y = *(uint32_t*)&h1;
                    ul.x = *(uint32_t*)&l0; ul.y = *(uint32_t*)&l1;
                    *(uint2*)(psm + P_AH + nbuf*P_ABUFB + arow*80 + akq*2) = uh;
                    *(uint2*)(psm + P_AL + nbuf*P_ABUFB + arow*80 + akq*2) = ul;
                }

                uint32_t baseAh = smb + P_AH + p*P_ABUFB;
                uint32_t baseAl = smb + P_AL + p*P_ABUFB;
                uint32_t baseBh = smb + P_BH + p*P_BBUFB;
                uint32_t baseBl = smb + P_BL + p*P_BBUFB;
                #pragma unroll
                for (int ks = 0; ks < 2; ks++){
                    uint32_t ah[4], al[4];
                    uint32_t eoA = (wm*16 + aRowOff)*80 + (ks*16 + aKOff)*2;
                    ldm4(ah, baseAh + eoA);
                    ldm4(al, baseAl + eoA);
                    uint32_t bh[4][2], bl[4][2];
                    #pragma unroll
                    for (int g = 0; g < 2; g++){
                        uint32_t eo = (wn*32 + g*16 + bNOff)*80 + (ks*16 + bKOff)*2;
                        uint32_t r[4];
                        ldm4(r, baseBh + eo);
                        bh[2*g][0]=r[0]; bh[2*g][1]=r[1]; bh[2*g+1][0]=r[2]; bh[2*g+1][1]=r[3];
                        ldm4(r, baseBl + eo);
                        bl[2*g][0]=r[0]; bl[2*g][1]=r[1]; bl[2*g+1][0]=r[2]; bl[2*g+1][1]=r[3];
                    }
                    #pragma unroll
                    for (int nt = 0; nt < 4; nt++){
                        mma16816(acc[nt], ah, bh[nt]);
                        mma16816(acc[nt], ah, bl[nt]);
                        mma16816(acc[nt], al, bh[nt]);
                    }
                }

                if (more) cp_wait0();
                __syncthreads();
                p ^= 1;
            }

            // ---- stage accs to Cs [32][132] ----
            #pragma unroll
            for (int nt = 0; nt < 4; nt++){
                int col = wn*32 + nt*8 + (lane & 3)*2;
                int r0  = wm*16 + (lane >> 2);
                Cs[r0*132 + col]     = acc[nt][0];
                Cs[r0*132 + col + 1] = acc[nt][1];
                Cs[(r0+8)*132 + col]     = acc[nt][2];
                Cs[(r0+8)*132 + col + 1] = acc[nt][3];
            }
            __syncthreads();

            // ---- LSTM epilogue: batched loads (MLP), then compute ----
            {
                float4 g4A[4], xgA[4];
                float cA[4], pA[4];
                int heA[4], spanA[4];
                #pragma unroll
                for (int e = 0; e < 4; e++){
                    int idx = tid + e*256;
                    int row = idx >> 5, jj = idx & 31;
                    int span = spn[row];
                    spanA[e] = span;
                    if (span < 0) continue;
                    g4A[e] = *(const float4*)&Cs[row*132 + jj*4];
                    int rank = dir ? (slen[row]-1-t) : t;
                    int j0 = (nb >> 2) + jj;
                    int he = (span*2 + dir)*HH + j0;
                    heA[e] = he;
                    xgA[e] = *(const float4*)(d_XG + (size_t)(span*ML + rank)*NCOL + dir*G4 + j0*4);
                    cA[e] = d_c[he];
                    pA[e] = d_pooled[he];
                }
                #pragma unroll
                for (int e = 0; e < 4; e++){
                    if (spanA[e] < 0) continue;
                    float gi = g4A[e].x+xgA[e].x, gf = g4A[e].y+xgA[e].y;
                    float gg = g4A[e].z+xgA[e].z, go = g4A[e].w+xgA[e].w;
                    float c = sigf(gf)*cA[e] + sigf(gi)*tanhf(gg);
                    float h = sigf(go)*tanhf(c);
                    int he = heA[e];
                    d_c[he] = c;
                    h_w[he] = h;
                    d_pooled[he] = pA[e] + h;
                }
            }
        }
    }
}

// ---------------- scoring GEMM: pooled [4096,512] x sembT [512,64] ----------------
__global__ void k_score(float* __restrict__ out){
    const int BM=64, BN=64, BK=16;
    int mBase = blockIdx.x * BM;
    __shared__ float As[BK][BM];
    __shared__ float Bs[BK][BN];
    int tid = threadIdx.x;
    float acc[4][4];
    #pragma unroll
    for (int i=0;i<4;i++)
        #pragma unroll
        for (int j=0;j<4;j++) acc[i][j]=0.f;
    int ty = tid >> 4, tx = tid & 15;
    for (int k0 = 0; k0 < DD; k0 += BK){
        {
            int row = tid >> 2;
            int kq  = (tid & 3) * 4;
            float4 v = *reinterpret_cast<const float4*>(d_pooled + (size_t)(mBase+row)*DD + k0 + kq);
            As[kq+0][row]=v.x; As[kq+1][row]=v.y; As[kq+2][row]=v.z; As[kq+3][row]=v.w;
        }
        {
            int kb = tid >> 4;
            int nq = (tid & 15) * 4;
            *reinterpret_cast<float4*>(&Bs[kb][nq]) =
                *reinterpret_cast<const float4*>(d_sembT + (size_t)(k0+kb)*NST + nq);
        }
        __syncthreads();
        #pragma unroll
        for (int kk=0; kk<BK; kk++){
            float a[4], b[4];
            *reinterpret_cast<float4*>(a) = *reinterpret_cast<float4*>(&As[kk][ty*4]);
            *reinterpret_cast<float4*>(b) = *reinterpret_cast<float4*>(&Bs[kk][tx*4]);
            #pragma unroll
            for (int i=0;i<4;i++)
                #pragma unroll
                for (int j=0;j<4;j++) acc[i][j] += a[i]*b[j];
        }
        __syncthreads();
    }
    #pragma unroll
    for (int i=0;i<4;i++){
        int r = mBase + ty*4 + i;
        #pragma unroll
        for (int j=0;j<4;j++)
            out[(size_t)r*NST + tx*4 + j] = acc[i][j];
    }
}

// ---------------- launch ----------------
extern "C" void kernel_launch(void* const* d_in, const int* in_sizes, int n_in,
                              void* d_out, int out_size){
    const float* lstm_repr = (const float*)d_in[0];
    const float* Wih_f     = (const float*)d_in[1];
    const float* Whh_f     = (const float*)d_in[2];
    const float* b_f       = (const float*)d_in[3];
    const float* Wih_b     = (const float*)d_in[4];
    const float* Whh_b     = (const float*)d_in[5];
    const float* b_b       = (const float*)d_in[6];
    const float* slot_emb  = (const float*)d_in[7];
    const int*   bio       = (const int*)d_in[8];
    float* out = (float*)d_out;

    cudaFuncSetAttribute(k_xg_mma, cudaFuncAttributeMaxDynamicSharedMemorySize, XSM_BYTES);
    cudaFuncSetAttribute(k_persist, cudaFuncAttributeMaxDynamicSharedMemorySize, P_BYTES);

    // order: persist is the 4th launch (= ncu capture slot)
    k_prep<<<1024, 256>>>(Wih_f, Wih_b, b_f, b_b, Whh_f, Whh_b, slot_emb);   // includes init
    k_pack<<<BB, 64>>>(bio);
    k_xg_mma<<<dim3(16, 256), 256, XSM_BYTES>>>(lstm_repr);
    k_persist<<<NBLK, 256, P_BYTES>>>();
    k_score<<<dim3(64), 256>>>(out);
}

// round 17
// speedup vs baseline: 1.7632x; 1.1652x over previous
#include <cuda_runtime.h>
#include <cuda_bf16.h>
#include <math.h>
#include <cstdint>

// ---------------- problem constants ----------------
#define BB   64
#define TT   512
#define DD   512
#define HH   256
#define MS   64
#define ML   8
#define NST  64
#define G4   1024
#define NCOL 2048
#define NSPAN (BB*MS)        // 4096
#define NPOS  (NSPAN*ML)     // 32768
#define NBLK 296             // persistent grid: 2 CTAs/SM, all co-resident (smem/regs verified)

// ---------------- device scratch ----------------
__device__ int   d_nvalid;
__device__ int   d_actcount[8];
__device__ int   g_arrive;
__device__ int   d_len_g[NSPAN];
__device__ int   d_srcidx_g[NPOS];
__device__ int   d_rowidx_g[NPOS];
__device__ int   d_actlist_g[8][NSPAN];
__device__ __nv_bfloat16 d_Wh[(size_t)NCOL*DD];     // W_ih hi split [n][k]
__device__ __nv_bfloat16 d_Wl[(size_t)NCOL*DD];     // lo
__device__ __nv_bfloat16 d_Whh_h[(size_t)NCOL*HH];  // W_hh hi split [n][k] gate-interleaved
__device__ __nv_bfloat16 d_Whh_l[(size_t)NCOL*HH];  // lo
__device__ float d_bcat[NCOL];
__device__ float d_sembT[DD*NST];
__device__ float d_XG[(size_t)NPOS*NCOL];    // gate-interleaved input gates
__device__ float d_hbuf[2][NSPAN*2*HH];      // ping-pong h
__device__ float d_c[NSPAN*2*HH];
__device__ float d_pooled[NSPAN*2*HH];

__device__ __forceinline__ float sigf(float x){ return 1.0f/(1.0f+__expf(-x)); }

__device__ __forceinline__ void cp16(void* dst, const void* src){
    unsigned int d = (unsigned int)__cvta_generic_to_shared(dst);
    asm volatile("cp.async.cg.shared.global [%0], [%1], 16;\n" :: "r"(d), "l"(src));
}
__device__ __forceinline__ void cp_commit(){ asm volatile("cp.async.commit_group;\n"); }
__device__ __forceinline__ void cp_wait0(){ asm volatile("cp.async.wait_group 0;\n"); }

__device__ __forceinline__ uint32_t smem_u32(const void* p){
    uint32_t a;
    asm("{ .reg .u64 t; cvta.to.shared.u64 t, %1; cvt.u32.u64 %0, t; }" : "=r"(a) : "l"(p));
    return a;
}
__device__ __forceinline__ void ldm4(uint32_t* r, uint32_t addr){
    asm volatile("ldmatrix.sync.aligned.m8n8.x4.shared.b16 {%0,%1,%2,%3}, [%4];"
        : "=r"(r[0]),"=r"(r[1]),"=r"(r[2]),"=r"(r[3]) : "r"(addr));
}
__device__ __forceinline__ void mma16816(float* c, const uint32_t* a, const uint32_t* b){
    asm volatile("mma.sync.aligned.m16n8k16.row.col.f32.bf16.bf16.f32 "
        "{%0,%1,%2,%3}, {%4,%5,%6,%7}, {%8,%9}, {%0,%1,%2,%3};"
        : "+f"(c[0]),"+f"(c[1]),"+f"(c[2]),"+f"(c[3])
        : "r"(a[0]),"r"(a[1]),"r"(a[2]),"r"(a[3]), "r"(b[0]),"r"(b[1]));
}
__device__ __forceinline__ int ld_acq(const int* p){
    int v;
    asm volatile("ld.acquire.gpu.b32 %0, [%1];" : "=r"(v) : "l"(p) : "memory");
    return v;
}

// ---------------- weight prep (includes init; launched FIRST) ----------------
__global__ void k_prep(const float* __restrict__ Wih_f, const float* __restrict__ Wih_b,
                       const float* __restrict__ bf,    const float* __restrict__ bbias,
                       const float* __restrict__ Whh_f, const float* __restrict__ Whh_b,
                       const float* __restrict__ semb){
    if (blockIdx.x == 0){
        if (threadIdx.x == 0){ d_nvalid = 0; g_arrive = 0; }
        if (threadIdx.x < 8)  d_actcount[threadIdx.x] = 0;
    }
    int i = blockIdx.x*blockDim.x + threadIdx.x;
    int stride = gridDim.x*blockDim.x;
    for (int idx = i; idx < NCOL*DD; idx += stride){
        int n = idx / DD, k = idx % DD;
        int dir = n >> 10, r = n & (G4-1);
        int row = (r & 3)*HH + (r >> 2);
        float w = dir ? Wih_b[row*DD + k] : Wih_f[row*DD + k];
        __nv_bfloat16 h = __float2bfloat16(w);
        d_Wh[idx] = h;
        d_Wl[idx] = __float2bfloat16(w - __bfloat162float(h));
    }
    for (int idx = i; idx < NCOL*HH; idx += stride){
        int n = idx >> 8, k = idx & (HH-1);
        int dir = n >> 10, r = n & (G4-1);
        int row = (r & 3)*HH + (r >> 2);
        float w = dir ? Whh_b[row*HH + k] : Whh_f[row*HH + k];
        __nv_bfloat16 h = __float2bfloat16(w);
        d_Whh_h[idx] = h;
        d_Whh_l[idx] = __float2bfloat16(w - __bfloat162float(h));
    }
    for (int idx = i; idx < NCOL; idx += stride){
        int dir = idx >> 10, r = idx & (G4-1);
        int row = (r & 3)*HH + (r >> 2);
        d_bcat[idx] = dir ? bbias[row] : bf[row];
    }
    for (int idx = i; idx < DD*NST; idx += stride){
        int k = idx / NST, n = idx % NST;
        d_sembT[idx] = semb[n*DD + k];
    }
}

// ---------------- span packing (smem-staged scan) ----------------
__global__ void k_pack(const int* __restrict__ bio){
    int b = blockIdx.x;
    __shared__ int s_bio[TT];
    __shared__ int s_tok[MS][ML];
    __shared__ int s_cnt[MS];
    int tid = threadIdx.x;          // 64
    s_cnt[tid] = 0;
    for (int i = tid; i < TT; i += 64) s_bio[i] = bio[b*TT + i];
    __syncthreads();
    if (tid == 0){
        int sid = -1;
        for (int t = 0; t < TT; t++){
            int tag = s_bio[t];
            if (tag == 1) sid++;
            if ((tag == 1 || tag == 2) && sid >= 0 && sid < MS){
                int r = s_cnt[sid];
                if (r < ML) s_tok[sid][r] = t;
                s_cnt[sid] = r + 1;
            }
        }
    }
    __syncthreads();
    int s = tid;
    int len = min(s_cnt[s], ML);
    int span = b*MS + s;
    d_len_g[span] = len;
    if (len > 0){
        int base = atomicAdd(&d_nvalid, len);
        for (int r = 0; r < len; r++){
            d_srcidx_g[base+r] = b*TT + s_tok[s][r];
            d_rowidx_g[base+r] = span*ML + r;
        }
        for (int t = 1; t < ML; t++){
            if (len > t){
                int k = atomicAdd(&d_actcount[t], 1);
                d_actlist_g[t][k] = span;
            }
        }
    }
}

// ---------------- xg GEMM via mma.sync bf16 3-pass split (exact R6 kernel) ----------------
#define XPAD 40
#define ABUF (128*XPAD)      // elements per buffer

__global__ void __launch_bounds__(256) k_xg_mma(const float* __restrict__ X){
    int M = d_nvalid;
    int mBase = blockIdx.y * 128;
    if (mBase >= M) return;
    int nBase = blockIdx.x * 128;

    extern __shared__ __nv_bfloat16 sm[];
    __nv_bfloat16* Ah = sm;                  // [2][128][XPAD]
    __nv_bfloat16* Al = Ah + 2*ABUF;
    __nv_bfloat16* Bh = Al + 2*ABUF;
    __nv_bfloat16* Bl = Bh + 2*ABUF;
    int* s_sidx = (int*)(Bl + 2*ABUF);
    int* s_ridx = s_sidx + 128;

    int tid = threadIdx.x;
    if (tid < 128){
        int m = mBase + tid;
        bool v = (m < M);
        s_sidx[tid] = v ? d_srcidx_g[m]*DD : 0;
        s_ridx[tid] = v ? d_rowidx_g[m] : -1;
    }
    __syncthreads();

    int lane = tid & 31, w = tid >> 5;
    int wm = w & 3, wn = w >> 2;

    int lrow = tid >> 1, lhalf = tid & 1;
    int aoffs = lrow*XPAD + lhalf*16;
    const __nv_bfloat16* BhSrc = d_Wh + (size_t)(nBase + lrow)*DD + lhalf*16;
    const __nv_bfloat16* BlSrc = d_Wl + (size_t)(nBase + lrow)*DD + lhalf*16;
    const float* ASrc = X + s_sidx[lrow] + lhalf*16;

    int aRowOff = lane & 15;
    int aKOff   = (lane >> 4) * 8;
    int bNOff   = (lane & 7) + ((lane >> 4) << 3);
    int bKOff   = ((lane >> 3) & 1) * 8;

    uint32_t smbA_h = smem_u32(Ah), smbA_l = smem_u32(Al);
    uint32_t smbB_h = smem_u32(Bh), smbB_l = smem_u32(Bl);

    float acc[2][8][4];
    #pragma unroll
    for (int i=0;i<2;i++)
        #pragma unroll
        for (int j=0;j<8;j++)
            #pragma unroll
            for (int q=0;q<4;q++) acc[i][j][q]=0.f;

    {
        cp16(Bh + aoffs, BhSrc);       cp16(Bh + aoffs + 8, BhSrc + 8);
        cp16(Bl + aoffs, BlSrc);       cp16(Bl + aoffs + 8, BlSrc + 8);
        cp_commit();
        float4 v0 = *(const float4*)(ASrc + 0);
        float4 v1 = *(const float4*)(ASrc + 4);
        float4 v2 = *(const float4*)(ASrc + 8);
        float4 v3 = *(const float4*)(ASrc + 12);
        float fv[16] = {v0.x,v0.y,v0.z,v0.w, v1.x,v1.y,v1.z,v1.w,
                        v2.x,v2.y,v2.z,v2.w, v3.x,v3.y,v3.z,v3.w};
        __nv_bfloat16 hh[16], ll[16];
        #pragma unroll
        for (int q=0;q<16;q++){
            hh[q] = __float2bfloat16(fv[q]);
            ll[q] = __float2bfloat16(fv[q] - __bfloat162float(hh[q]));
        }
        *(uint4*)(Ah + aoffs)     = *(uint4*)(hh);
        *(uint4*)(Ah + aoffs + 8) = *(uint4*)(hh+8);
        *(uint4*)(Al + aoffs)     = *(uint4*)(ll);
        *(uint4*)(Al + aoffs + 8) = *(uint4*)(ll+8);
        cp_wait0();
        __syncthreads();
    }

    int p = 0;
    for (int kc = 0; kc < 16; kc++){
        float fv[16];
        bool more = (kc < 15);
        if (more){
            int nb = p ^ 1;
            int k0 = (kc+1)*32;
            int doffs = nb*ABUF + aoffs;
            cp16(Bh + doffs, BhSrc + k0);       cp16(Bh + doffs + 8, BhSrc + k0 + 8);
            cp16(Bl + doffs, BlSrc + k0);       cp16(Bl + doffs + 8, BlSrc + k0 + 8);
            cp_commit();
            float4 v0 = *(const float4*)(ASrc + k0 + 0);
            float4 v1 = *(const float4*)(ASrc + k0 + 4);
            float4 v2 = *(const float4*)(ASrc + k0 + 8);
            float4 v3 = *(const float4*)(ASrc + k0 + 12);
            fv[0]=v0.x; fv[1]=v0.y; fv[2]=v0.z; fv[3]=v0.w;
            fv[4]=v1.x; fv[5]=v1.y; fv[6]=v1.z; fv[7]=v1.w;
            fv[8]=v2.x; fv[9]=v2.y; fv[10]=v2.z; fv[11]=v2.w;
            fv[12]=v3.x; fv[13]=v3.y; fv[14]=v3.z; fv[15]=v3.w;
        }

        uint32_t baseAh = smbA_h + p*ABUF*2;
        uint32_t baseAl = smbA_l + p*ABUF*2;
        uint32_t baseBh = smbB_h + p*ABUF*2;
        uint32_t baseBl = smbB_l + p*ABUF*2;
        #pragma unroll
        for (int ks = 0; ks < 2; ks++){
            uint32_t ah[2][4], al[2][4];
            #pragma unroll
            for (int mt = 0; mt < 2; mt++){
                uint32_t eo = ((wm*32 + mt*16 + aRowOff)*XPAD + ks*16 + aKOff)*2;
                ldm4(ah[mt], baseAh + eo);
                ldm4(al[mt], baseAl + eo);
            }
            uint32_t bh[8][2], bl[8][2];
            #pragma unroll
            for (int g = 0; g < 4; g++){
                uint32_t eo = ((wn*64 + g*16 + bNOff)*XPAD + ks*16 + bKOff)*2;
                uint32_t r[4];
                ldm4(r, baseBh + eo);
                bh[2*g][0]=r[0]; bh[2*g][1]=r[1]; bh[2*g+1][0]=r[2]; bh[2*g+1][1]=r[3];
                ldm4(r, baseBl + eo);
                bl[2*g][0]=r[0]; bl[2*g][1]=r[1]; bl[2*g+1][0]=r[2]; bl[2*g+1][1]=r[3];
            }
            #pragma unroll
            for (int mt = 0; mt < 2; mt++)
                #pragma unroll
                for (int nt = 0; nt < 8; nt++){
                    mma16816(acc[mt][nt], ah[mt], bh[nt]);
                    mma16816(acc[mt][nt], ah[mt], bl[nt]);
                    mma16816(acc[mt][nt], al[mt], bh[nt]);
                }
        }

        if (more){
            int nb = p ^ 1;
            int doffs = nb*ABUF + aoffs;
            __nv_bfloat16 hh[16], ll[16];
            #pragma unroll
            for (int q=0;q<16;q++){
                hh[q] = __float2bfloat16(fv[q]);
                ll[q] = __float2bfloat16(fv[q] - __bfloat162float(hh[q]));
            }
            *(uint4*)(Ah + doffs)     = *(uint4*)(hh);
            *(uint4*)(Ah + doffs + 8) = *(uint4*)(hh+8);
            *(uint4*)(Al + doffs)     = *(uint4*)(ll);
            *(uint4*)(Al + doffs + 8) = *(uint4*)(ll+8);
            cp_wait0();
        }
        __syncthreads();
        p ^= 1;
    }

    #pragma unroll
    for (int mt = 0; mt < 2; mt++){
        int rl0 = wm*32 + mt*16 + (lane >> 2);
        #pragma unroll
        for (int half = 0; half < 2; half++){
            int rl = rl0 + half*8;
            int grow = s_ridx[rl];
            if (grow < 0) continue;
            float* dst = d_XG + (size_t)grow*NCOL + nBase;
            #pragma unroll
            for (int nt = 0; nt < 8; nt++){
                int col = wn*64 + nt*8 + (lane & 3)*2;
                float2 b2 = *(const float2*)(d_bcat + nBase + col);
                float2 o;
                o.x = acc[mt][nt][half*2+0] + b2.x;
                o.y = acc[mt][nt][half*2+1] + b2.y;
                *(float2*)(dst + col) = o;
            }
        }
    }
}
#define XSM_BYTES (8*ABUF*2 + 256*4)

// ---------------- persistent recurrence (2 CTAs/SM, MLP-batched) ----------------
// tile: BM=32 spans x BN=128 gate-cols x K=256, K-chunk 32, bf16 hi/lo 3-pass mma.
#define P_AH 0                       // [2][32][40] bf16 = 5120
#define P_AL 5120
#define P_BH 10240                   // [2][128][40] bf16 = 20480
#define P_BL 30720
#define P_CS 51200                   // [32][132] float = 16896
#define P_SPN 68096
#define P_AOFF 68224
#define P_SLEN 68352
#define P_BYTES 68480
#define P_ABUFB 2560                 // A per-buffer bytes (32*80)
#define P_BBUFB 10240                // B per-buffer bytes (128*80)

__global__ void __launch_bounds__(256) k_persist(){
    extern __shared__ char psm[];
    float* Cs = (float*)(psm + P_CS);            // [32][132]
    int* spn  = (int*)(psm + P_SPN);
    int* aoff = (int*)(psm + P_AOFF);
    int* slen = (int*)(psm + P_SLEN);
    uint32_t smb = smem_u32(psm);
    int tid = threadIdx.x, bid = blockIdx.x;
    int lane = tid & 31, w = tid >> 5;
    int wm = w & 1, wn = w >> 1;                 // 2 m-groups x 4 n-groups

    // ---- phase 0: step 0 pointwise, 4-way batched loads (MLP) ----
    {
        const int TOT = NSPAN*2*HH;
        const int stride = NBLK*256;
        for (int base = bid*256 + tid; base < TOT; base += 4*stride){
            int lenA[4]; bool vA[4]; float4 gA[4];
            #pragma unroll
            for (int r = 0; r < 4; r++){
                int idx = base + r*stride;
                vA[r] = (idx < TOT);
                lenA[r] = vA[r] ? d_len_g[idx >> 9] : 0;
            }
            #pragma unroll
            for (int r = 0; r < 4; r++){
                if (!vA[r] || lenA[r] == 0) continue;
                int idx = base + r*stride;
                int rem = idx & 511;
                int dir = rem >> 8, j = rem & 255, span = idx >> 9;
                int rank = dir ? (lenA[r]-1) : 0;
                gA[r] = *(const float4*)(d_XG + (size_t)(span*ML + rank)*NCOL + dir*G4 + j*4);
            }
            #pragma unroll
            for (int r = 0; r < 4; r++){
                if (!vA[r]) continue;
                int idx = base + r*stride;
                if (lenA[r] == 0){
                    d_hbuf[0][idx] = 0.f; d_c[idx] = 0.f; d_pooled[idx] = 0.f;
                } else {
                    float c = sigf(gA[r].x) * tanhf(gA[r].z);
                    float h = sigf(gA[r].w) * tanhf(c);
                    d_c[idx] = c; d_hbuf[0][idx] = h; d_pooled[idx] = h;
                }
            }
        }
    }

    int aRowOff = lane & 15;
    int aKOff   = (lane >> 4) * 8;
    int bNOff   = (lane & 7) + ((lane >> 4) << 3);
    int bKOff   = ((lane >> 3) & 1) * 8;
    int arow = tid >> 3, akq = (tid & 7) * 4;    // A loader: row 0..31, 4 floats each

    for (int t = 1; t < ML; t++){
        // ---- global epoch barrier #t (release-arrive, acquire-poll) ----
        __syncthreads();
        if (tid == 0){
            __threadfence();
            atomicAdd(&g_arrive, 1);
            while (ld_acq(&g_arrive) < t*NBLK) { }
        }
        __syncthreads();

        int cnt = d_actcount[t];
        if (cnt <= 0) continue;
        const float* __restrict__ h_r = d_hbuf[(t-1)&1];
        float* __restrict__ h_w = d_hbuf[t&1];
        int nmt  = (cnt + 31) >> 5;
        int ntot = nmt * 16;

        for (int tile = bid; tile < ntot; tile += NBLK){
            int mt  = tile >> 4;
            int ct  = tile & 15;
            int dir = ct >> 3;
            int nb  = (ct & 7) * 128;

            __syncthreads();          // previous tile's smem fully consumed
            if (tid < 32){
                int m = mt*32 + tid;
                int span = (m < cnt) ? d_actlist_g[t][m] : -1;
                spn[tid] = span;
                int s0 = (span >= 0) ? span : 0;
                aoff[tid] = (s0*2 + dir)*HH;
                slen[tid] = d_len_g[s0];
            }
            __syncthreads();

            const __nv_bfloat16* WhhH = d_Whh_h + (size_t)(dir*G4 + nb)*HH;
            const __nv_bfloat16* WhhL = d_Whh_l + (size_t)(dir*G4 + nb)*HH;

            // ---- prologue: chunk 0 into buffer 0 ----
            {
                #pragma unroll
                for (int li = 0; li < 2; li++){
                    int lin = tid + li*256;
                    int row = lin >> 2, seg = lin & 3;
                    cp16(psm + P_BH + row*80 + seg*16, WhhH + (size_t)row*HH + seg*8);
                    cp16(psm + P_BL + row*80 + seg*16, WhhL + (size_t)row*HH + seg*8);
                }
                cp_commit();
                float4 av = *(const float4*)(h_r + aoff[arow] + akq);
                __nv_bfloat162 h0 = __floats2bfloat162_rn(av.x, av.y);
                __nv_bfloat162 h1 = __floats2bfloat162_rn(av.z, av.w);
                __nv_bfloat162 l0 = __floats2bfloat162_rn(av.x - __bfloat162float(h0.x), av.y - __bfloat162float(h0.y));
                __nv_bfloat162 l1 = __floats2bfloat162_rn(av.z - __bfloat162float(h1.x), av.w - __bfloat162float(h1.y));
                uint2 uh, ul;
                uh.x = *(uint32_t*)&h0; uh.y = *(uint32_t*)&h1;
                ul.x = *(uint32_t*)&l0; ul.y = *(uint32_t*)&l1;
                *(uint2*)(psm + P_AH + arow*80 + akq*2) = uh;
                *(uint2*)(psm + P_AL + arow*80 + akq*2) = ul;
                cp_wait0();
                __syncthreads();
            }

            float acc[4][4];
            #pragma unroll
            for (int i=0;i<4;i++)
                #pragma unroll
                for (int q=0;q<4;q++) acc[i][q]=0.f;

            int p = 0;
            for (int kc = 0; kc < 8; kc++){
                bool more = (kc < 7);
                if (more){
                    int nbuf = p ^ 1;
                    int k0 = (kc+1)*32;
                    #pragma unroll
                    for (int li = 0; li < 2; li++){
                        int lin = tid + li*256;
                        int row = lin >> 2, seg = lin & 3;
                        cp16(psm + P_BH + nbuf*P_BBUFB + row*80 + seg*16, WhhH + (size_t)row*HH + k0 + seg*8);
                        cp16(psm + P_BL + nbuf*P_BBUFB + row*80 + seg*16, WhhL + (size_t)row*HH + k0 + seg*8);
                    }
                    cp_commit();
                    float4 av = *(const float4*)(h_r + aoff[arow] + k0 + akq);
                    __nv_bfloat162 h0 = __floats2bfloat162_rn(av.x, av.y);
                    __nv_bfloat162 h1 = __floats2bfloat162_rn(av.z, av.w);
                    __nv_bfloat162 l0 = __floats2bfloat162_rn(av.x - __bfloat162float(h0.x), av.y - __bfloat162float(h0.y));
                    __nv_bfloat162 l1 = __floats2bfloat162_rn(av.z - __bfloat162float(h1.x), av.w - __bfloat162float(h1.y));
                    uint2 uh, ul;
                    uh.x = *(uint32_t*)&h0; uh.y = *(uint32_t*)&h1;
                    ul.x = *(uint32_t*)&l0; ul.y = *(uint32_t*)&l1;
                    *(uint2*)(psm + P_AH + nbuf*P_ABUFB + arow*80 + akq*2) = uh;
                    *(uint2*)(psm + P_AL + nbuf*P_ABUFB + arow*80 + akq*2) = ul;
                }

                uint32_t baseAh = smb + P_AH + p*P_ABUFB;
                uint32_t baseAl = smb + P_AL + p*P_ABUFB;
                uint32_t baseBh = smb + P_BH + p*P_BBUFB;
                uint32_t baseBl = smb + P_BL + p*P_BBUFB;
                #pragma unroll
                for (int ks = 0; ks < 2; ks++){
                    uint32_t ah[4], al[4];
                    uint32_t eoA = (wm*16 + aRowOff)*80 + (ks*16 + aKOff)*2;
                    ldm4(ah, baseAh + eoA);
                    ldm4(al, baseAl + eoA);
                    uint32_t bh[4][2], bl[4][2];
                    #pragma unroll
                    for (int g = 0; g < 2; g++){
                        uint32_t eo = (wn*32 + g*16 + bNOff)*80 + (ks*16 + bKOff)*2;
                        uint32_t r[4];
                        ldm4(r, baseBh + eo);
                        bh[2*g][0]=r[0]; bh[2*g][1]=r[1]; bh[2*g+1][0]=r[2]; bh[2*g+1][1]=r[3];
                        ldm4(r, baseBl + eo);
                        bl[2*g][0]=r[0]; bl[2*g][1]=r[1]; bl[2*g+1][0]=r[2]; bl[2*g+1][1]=r[3];
                    }
                    #pragma unroll
                    for (int nt = 0; nt < 4; nt++){
                        mma16816(acc[nt], ah, bh[nt]);
                        mma16816(acc[nt], ah, bl[nt]);
                        mma16816(acc[nt], al, bh[nt]);
                    }
                }

                if (more) cp_wait0();
                __syncthreads();
                p ^= 1;
            }

            // ---- stage accs to Cs [32][132] ----
            #pragma unroll
            for (int nt = 0; nt < 4; nt++){
                int col = wn*32 + nt*8 + (lane & 3)*2;
                int r0  = wm*16 + (lane >> 2);
                Cs[r0*132 + col]     = acc[nt][0];
                Cs[r0*132 + col + 1] = acc[nt][1];
                Cs[(r0+8)*132 + col]     = acc[nt][2];
                Cs[(r0+8)*132 + col + 1] = acc[nt][3];
            }
            __syncthreads();

            // ---- LSTM epilogue: batched loads (MLP), then compute ----
            {
                float4 g4A[4], xgA[4];
                float cA[4], pA[4];
                int heA[4], spanA[4];
                #pragma unroll
                for (int e = 0; e < 4; e++){
                    int idx = tid + e*256;
                    int row = idx >> 5, jj = idx & 31;
                    int span = spn[row];
                    spanA[e] = span;
                    if (span < 0) continue;
                    g4A[e] = *(const float4*)&Cs[row*132 + jj*4];
                    int rank = dir ? (slen[row]-1-t) : t;
                    int j0 = (nb >> 2) + jj;
                    int he = (span*2 + dir)*HH + j0;
                    heA[e] = he;
                    xgA[e] = *(const float4*)(d_XG + (size_t)(span*ML + rank)*NCOL + dir*G4 + j0*4);
                    cA[e] = d_c[he];
                    pA[e] = d_pooled[he];
                }
                #pragma unroll
                for (int e = 0; e < 4; e++){
                    if (spanA[e] < 0) continue;
                    float gi = g4A[e].x+xgA[e].x, gf = g4A[e].y+xgA[e].y;
                    float gg = g4A[e].z+xgA[e].z, go = g4A[e].w+xgA[e].w;
                    float c = sigf(gf)*cA[e] + sigf(gi)*tanhf(gg);
                    float h = sigf(go)*tanhf(c);
                    int he = heA[e];
                    d_c[he] = c;
                    h_w[he] = h;
                    d_pooled[he] = pA[e] + h;
                }
            }
        }
    }
}

// ---------------- scoring GEMM: pooled [4096,512] x sembT [512,64] ----------------
__global__ void k_score(float* __restrict__ out){
    const int BM=64, BN=64, BK=16;
    int mBase = blockIdx.x * BM;
    __shared__ float As[BK][BM];
    __shared__ float Bs[BK][BN];
    int tid = threadIdx.x;
    float acc[4][4];
    #pragma unroll
    for (int i=0;i<4;i++)
        #pragma unroll
        for (int j=0;j<4;j++) acc[i][j]=0.f;
    int ty = tid >> 4, tx = tid & 15;
    for (int k0 = 0; k0 < DD; k0 += BK){
        {
            int row = tid >> 2;
            int kq  = (tid & 3) * 4;
            float4 v = *reinterpret_cast<const float4*>(d_pooled + (size_t)(mBase+row)*DD + k0 + kq);
            As[kq+0][row]=v.x; As[kq+1][row]=v.y; As[kq+2][row]=v.z; As[kq+3][row]=v.w;
        }
        {
            int kb = tid >> 4;
            int nq = (tid & 15) * 4;
            *reinterpret_cast<float4*>(&Bs[kb][nq]) =
                *reinterpret_cast<const float4*>(d_sembT + (size_t)(k0+kb)*NST + nq);
        }
        __syncthreads();
        #pragma unroll
        for (int kk=0; kk<BK; kk++){
            float a[4], b[4];
            *reinterpret_cast<float4*>(a) = *reinterpret_cast<float4*>(&As[kk][ty*4]);
            *reinterpret_cast<float4*>(b) = *reinterpret_cast<float4*>(&Bs[kk][tx*4]);
            #pragma unroll
            for (int i=0;i<4;i++)
                #pragma unroll
                for (int j=0;j<4;j++) acc[i][j] += a[i]*b[j];
        }
        __syncthreads();
    }
    #pragma unroll
    for (int i=0;i<4;i++){
        int r = mBase + ty*4 + i;
        #pragma unroll
        for (int j=0;j<4;j++)
            out[(size_t)r*NST + tx*4 + j] = acc[i][j];
    }
}

// ---------------- launch ----------------
extern "C" void kernel_launch(void* const* d_in, const int* in_sizes, int n_in,
                              void* d_out, int out_size){
    const float* lstm_repr = (const float*)d_in[0];
    const float* Wih_f     = (const float*)d_in[1];
    const float* Whh_f     = (const float*)d_in[2];
    const float* b_f       = (const float*)d_in[3];
    const float* Wih_b     = (const float*)d_in[4];
    const float* Whh_b     = (const float*)d_in[5];
    const float* b_b       = (const float*)d_in[6];
    const float* slot_emb  = (const float*)d_in[7];
    const int*   bio       = (const int*)d_in[8];
    float* out = (float*)d_out;

    cudaFuncSetAttribute(k_xg_mma, cudaFuncAttributeMaxDynamicSharedMemorySize, XSM_BYTES);
    cudaFuncSetAttribute(k_persist, cudaFuncAttributeMaxDynamicSharedMemorySize, P_BYTES);

    // order: persist is the 4th launch (= ncu capture slot)
    k_prep<<<1024, 256>>>(Wih_f, Wih_b, b_f, b_b, Whh_f, Whh_b, slot_emb);   // includes init
    k_pack<<<BB, 64>>>(bio);
    k_xg_mma<<<dim3(16, 256), 256, XSM_BYTES>>>(lstm_repr);
    k_persist<<<NBLK, 256, P_BYTES>>>();
    k_score<<<dim3(64), 256>>>(out);
}